// round 1
// baseline (speedup 1.0000x reference)
#include <cuda_runtime.h>
#include <cuda_bf16.h>

// Problem constants (fixed by the reference)
#define NN 10000          // nodes
#define DD 784            // input feature dim
#define KK 16             // neighbors+1
#define EE (NN * (KK-1))  // edges = 150000
#define HH 128            // hidden width

// ---------------- scratch (static device globals; no runtime alloc) -------
__device__ float g_xw    [NN * HH];   // x @ W1x   (also reused as hw2)
__device__ float g_hbar  [NN * HH];   // mean hidden per node (both layers)
__device__ float g_agg1  [NN * DD];   // layer-1 aggregated message
__device__ float g_hidden[NN * HH];   // node-MLP hidden (both layers)
__device__ float g_h     [NN * HH];   // layer-1 node output
__device__ float g_agg2  [NN * HH];   // layer-2 aggregated message
__device__ float g_proj  [NN * 2];    // final projection
__device__ int   g_cnt   [NN];        // in-degree per src node
__device__ int   g_offs  [NN];        // CSR offsets
__device__ int   g_pos   [NN];        // fill cursors
__device__ float g_bucket[EE];        // per-node edge_attr lists (CSR payload)

// ---------------- CSR construction ----------------------------------------
__global__ void zero_kernel() {
    int i = blockIdx.x * blockDim.x + threadIdx.x;
    if (i < NN) { g_cnt[i] = 0; g_pos[i] = 0; }
}

__global__ void count_kernel(const int* __restrict__ idxs) {
    int e = blockIdx.x * blockDim.x + threadIdx.x;
    if (e < EE) atomicAdd(&g_cnt[idxs[e]], 1);
}

// exclusive scan of g_cnt -> g_offs, single block of 1024
__global__ void scan_kernel() {
    __shared__ int buf[1024];
    __shared__ int carry;
    int tid = threadIdx.x;
    if (tid == 0) carry = 0;
    __syncthreads();
    for (int base = 0; base < NN; base += 1024) {
        int i = base + tid;
        int v = (i < NN) ? g_cnt[i] : 0;
        buf[tid] = v;
        __syncthreads();
        for (int off = 1; off < 1024; off <<= 1) {
            int t = (tid >= off) ? buf[tid - off] : 0;
            __syncthreads();
            buf[tid] += t;
            __syncthreads();
        }
        if (i < NN) g_offs[i] = carry + buf[tid] - v;   // exclusive
        __syncthreads();
        if (tid == 0) carry += buf[1023];
        __syncthreads();
    }
}

__global__ void fill_kernel(const int* __restrict__ idxs,
                            const float* __restrict__ ea) {
    int e = blockIdx.x * blockDim.x + threadIdx.x;
    if (e < EE) {
        int s = idxs[e];
        int p = atomicAdd(&g_pos[s], 1);
        g_bucket[g_offs[s] + p] = ea[e];
    }
}

// ---------------- generic SGEMM (dual-source concat, bias, relu, mask) ----
// C[M,N] = (A1[M,K1] @ B1[K1,N]) + (A2[M,K2] @ B2[K2,N]) (+bias)(relu)(mask)
#define BM 64
#define BN 64
#define BK 16
__global__ void sgemm(const float* __restrict__ A1, int lda1,
                      const float* __restrict__ B1, int ldb1, int K1,
                      const float* __restrict__ A2, int lda2,
                      const float* __restrict__ B2, int ldb2, int K2,
                      const float* __restrict__ bias,
                      const int* __restrict__ mask, int do_relu,
                      float* __restrict__ C, int M, int N) {
    __shared__ float As[BK][BM + 1];
    __shared__ float Bs[BK][BN + 1];
    int bm = blockIdx.y * BM;
    int bn = blockIdx.x * BN;
    int tid = threadIdx.x;            // 0..255
    int tx = tid & 15;                // 0..15 -> col group
    int ty = tid >> 4;                // 0..15 -> row group
    float acc[4][4] = {};

    for (int s = 0; s < 2; s++) {
        const float* A = s ? A2 : A1;
        const float* B = s ? B2 : B1;
        int K   = s ? K2   : K1;
        int lda = s ? lda2 : lda1;
        int ldb = s ? ldb2 : ldb1;
        if (A == nullptr || K == 0) continue;
        for (int k0 = 0; k0 < K; k0 += BK) {
            // A tile: BM x BK (1024 elems / 256 threads)
            #pragma unroll
            for (int i = tid; i < BM * BK; i += 256) {
                int m = i >> 4, kk = i & 15;
                int gm = bm + m, gk = k0 + kk;
                As[kk][m] = (gm < M && gk < K) ? A[(size_t)gm * lda + gk] : 0.f;
            }
            // B tile: BK x BN
            #pragma unroll
            for (int i = tid; i < BK * BN; i += 256) {
                int kk = i >> 6, n = i & 63;
                int gk = k0 + kk, gn = bn + n;
                Bs[kk][n] = (gk < K && gn < N) ? B[(size_t)gk * ldb + gn] : 0.f;
            }
            __syncthreads();
            #pragma unroll
            for (int kk = 0; kk < BK; kk++) {
                float a[4], b[4];
                #pragma unroll
                for (int i = 0; i < 4; i++) a[i] = As[kk][ty * 4 + i];
                #pragma unroll
                for (int j = 0; j < 4; j++) b[j] = Bs[kk][tx * 4 + j];
                #pragma unroll
                for (int i = 0; i < 4; i++)
                    #pragma unroll
                    for (int j = 0; j < 4; j++)
                        acc[i][j] = fmaf(a[i], b[j], acc[i][j]);
            }
            __syncthreads();
        }
    }
    // epilogue
    #pragma unroll
    for (int i = 0; i < 4; i++) {
        int gm = bm + ty * 4 + i;
        if (gm >= M) continue;
        bool zero_row = (mask != nullptr) && (mask[gm] == 0);
        #pragma unroll
        for (int j = 0; j < 4; j++) {
            int gn = bn + tx * 4 + j;
            if (gn >= N) continue;
            float v = acc[i][j];
            if (bias) v += bias[gn];
            if (do_relu) v = fmaxf(v, 0.f);
            if (zero_row) v = 0.f;
            C[(size_t)gm * N + gn] = v;
        }
    }
}

// ---------------- per-node edge aggregation --------------------------------
// hbar[m,j] = mean over incident edges of relu(xw[m,j] + b[j] + a_e * we[j])
__global__ void edge_agg(const float* __restrict__ xw,
                         const float* __restrict__ we,
                         const float* __restrict__ b,
                         float* __restrict__ hbar) {
    __shared__ float sa[128];
    int m = blockIdx.x;
    int j = threadIdx.x;              // 0..127
    int deg = g_cnt[m];
    int start = g_offs[m];
    float xj = xw[m * HH + j] + b[j];
    float wj = we[j];
    float s = 0.f;
    for (int base = 0; base < deg; base += 128) {
        int c = min(128, deg - base);
        if (j < c) sa[j] = g_bucket[start + base + j];
        __syncthreads();
        for (int t = 0; t < c; t++)
            s += fmaxf(fmaf(sa[t], wj, xj), 0.f);
        __syncthreads();
    }
    hbar[m * HH + j] = deg ? s / (float)deg : 0.f;
}

// ---------------- final projection [N,128] @ [128,2] + b -------------------
__global__ void proj_kernel(const float* __restrict__ hidden,
                            const float* __restrict__ W,   // [128,2]
                            const float* __restrict__ b,
                            float* __restrict__ proj) {
    int gt = blockIdx.x * blockDim.x + threadIdx.x;
    int warp = gt >> 5;
    int lane = gt & 31;
    if (warp >= NN) return;
    float s0 = 0.f, s1 = 0.f;
    for (int j = lane; j < 128; j += 32) {
        float hv = hidden[warp * HH + j];
        s0 = fmaf(hv, W[j * 2 + 0], s0);
        s1 = fmaf(hv, W[j * 2 + 1], s1);
    }
    #pragma unroll
    for (int o = 16; o > 0; o >>= 1) {
        s0 += __shfl_down_sync(0xFFFFFFFFu, s0, o);
        s1 += __shfl_down_sync(0xFFFFFFFFu, s1, o);
    }
    if (lane == 0) {
        proj[warp * 2 + 0] = s0 + b[0];
        proj[warp * 2 + 1] = s1 + b[1];
    }
}

// ---------------- pairwise squared distances -------------------------------
__global__ void dist_kernel(const float* __restrict__ proj,
                            const int* __restrict__ idxs,
                            float* __restrict__ out) {
    int i = blockIdx.x * blockDim.x + threadIdx.x;
    if (i >= EE) return;
    int n  = i / (KK - 1);
    int nb = idxs[i];
    float dx = proj[n * 2 + 0] - proj[nb * 2 + 0];
    float dy = proj[n * 2 + 1] - proj[nb * 2 + 1];
    out[i] = dx * dx + dy * dy;
}

// ---------------- launch ---------------------------------------------------
extern "C" void kernel_launch(void* const* d_in, const int* in_sizes, int n_in,
                              void* d_out, int out_size) {
    const float* x     = (const float*)d_in[0];
    const float* ea    = (const float*)d_in[1];
    const int*   idxs  = (const int*)  d_in[2];
    const float* l1mw1 = (const float*)d_in[3];
    const float* l1mb1 = (const float*)d_in[4];
    const float* l1mw2 = (const float*)d_in[5];
    const float* l1mb2 = (const float*)d_in[6];
    const float* l1nw1 = (const float*)d_in[7];
    const float* l1nb1 = (const float*)d_in[8];
    const float* l1nw2 = (const float*)d_in[9];
    const float* l1nb2 = (const float*)d_in[10];
    const float* l2mw1 = (const float*)d_in[11];
    const float* l2mb1 = (const float*)d_in[12];
    const float* l2mw2 = (const float*)d_in[13];
    const float* l2mb2 = (const float*)d_in[14];
    const float* l2nw1 = (const float*)d_in[15];
    const float* l2nb1 = (const float*)d_in[16];
    const float* l2nw2 = (const float*)d_in[17];
    const float* l2nb2 = (const float*)d_in[18];
    float* out = (float*)d_out;

    float *xw, *hbar, *agg1, *hidden, *h, *agg2, *proj;
    int *cnt;
    cudaGetSymbolAddress((void**)&xw,     g_xw);
    cudaGetSymbolAddress((void**)&hbar,   g_hbar);
    cudaGetSymbolAddress((void**)&agg1,   g_agg1);
    cudaGetSymbolAddress((void**)&hidden, g_hidden);
    cudaGetSymbolAddress((void**)&h,      g_h);
    cudaGetSymbolAddress((void**)&agg2,   g_agg2);
    cudaGetSymbolAddress((void**)&proj,   g_proj);
    cudaGetSymbolAddress((void**)&cnt,    g_cnt);

    auto gemm_grid = [](int M, int N) {
        return dim3((unsigned)((N + BN - 1) / BN), (unsigned)((M + BM - 1) / BM));
    };

    // CSR over src = idxs.flatten()
    zero_kernel <<<(NN + 255) / 256, 256>>>();
    count_kernel<<<(EE + 255) / 256, 256>>>(idxs);
    scan_kernel <<<1, 1024>>>();
    fill_kernel <<<(EE + 255) / 256, 256>>>(idxs, ea);

    // ----- layer 1 -----
    // xw = x @ W1x                         [N,128]
    sgemm<<<gemm_grid(NN, HH), 256>>>(x, DD, l1mw1, HH, DD,
                                      nullptr, 0, nullptr, 0, 0,
                                      nullptr, nullptr, 0, xw, NN, HH);
    // hbar = mean_e relu(xw[src] + a*we + b1)
    edge_agg<<<NN, HH>>>(xw, l1mw1 + (size_t)DD * HH, l1mb1, hbar);
    // agg1 = (hbar @ W2 + b2) masked       [N,784]
    sgemm<<<gemm_grid(NN, DD), 256>>>(hbar, HH, l1mw2, DD, HH,
                                      nullptr, 0, nullptr, 0, 0,
                                      l1mb2, cnt, 0, agg1, NN, DD);
    // hidden = relu(x@W1a + agg1@W1b + b1) [N,128]
    sgemm<<<gemm_grid(NN, HH), 256>>>(x, DD, l1nw1, HH, DD,
                                      agg1, DD, l1nw1 + (size_t)DD * HH, HH, DD,
                                      l1nb1, nullptr, 1, hidden, NN, HH);
    // h = hidden @ W2 + b2                 [N,128]
    sgemm<<<gemm_grid(NN, HH), 256>>>(hidden, HH, l1nw2, HH, HH,
                                      nullptr, 0, nullptr, 0, 0,
                                      l1nb2, nullptr, 0, h, NN, HH);

    // ----- layer 2 -----
    // hw2 = h @ W1h (reuse xw buffer)
    sgemm<<<gemm_grid(NN, HH), 256>>>(h, HH, l2mw1, HH, HH,
                                      nullptr, 0, nullptr, 0, 0,
                                      nullptr, nullptr, 0, xw, NN, HH);
    edge_agg<<<NN, HH>>>(xw, l2mw1 + (size_t)HH * HH, l2mb1, hbar);
    sgemm<<<gemm_grid(NN, HH), 256>>>(hbar, HH, l2mw2, HH, HH,
                                      nullptr, 0, nullptr, 0, 0,
                                      l2mb2, cnt, 0, agg2, NN, HH);
    sgemm<<<gemm_grid(NN, HH), 256>>>(h, HH, l2nw1, HH, HH,
                                      agg2, HH, l2nw1 + (size_t)HH * HH, HH, HH,
                                      l2nb1, nullptr, 1, hidden, NN, HH);
    proj_kernel<<<(NN * 32 + 255) / 256, 256>>>(hidden, l2nw2, l2nb2, proj);

    // ----- output -----
    dist_kernel<<<(EE + 255) / 256, 256>>>(proj, idxs, out);
}

// round 2
// speedup vs baseline: 2.2289x; 2.2289x over previous
#include <cuda_runtime.h>
#include <cuda_bf16.h>

// Problem constants (fixed by the reference)
#define NN 10000          // nodes
#define DD 784            // input feat dim
#define KK 16             // neighbors+1
#define EE (NN * (KK-1))  // edges = 150000
#define HH 128            // hidden width

// ---------------- scratch (static device globals) --------------------------
__device__ float g_XW    [NN * 256];  // x @ [W1x_msg | W1a_node]
__device__ float g_HW2   [NN * 256];  // h @ [W1x2 | W1a2]  (folded)
__device__ float g_hbar  [NN * HH];   // mean edge-hidden per node (both layers)
__device__ float g_hidden[NN * HH];   // node-MLP hidden (both layers)
__device__ float g_proj  [NN * 2];
__device__ float g_Wf1   [HH * HH];   // l1: W2_msg @ W1b_node
__device__ float g_Wf2   [HH * HH];   // l2: W2_msg @ W1b_node
__device__ float g_Wh    [HH * 256];  // l1nw2 @ [l2 W1x | l2 W1a]
__device__ float g_bf1   [HH];
__device__ float g_bf2   [HH];
__device__ float g_bh    [256];
__device__ int   g_cnt   [NN];
__device__ int   g_offs  [NN];
__device__ int   g_pos   [NN];
__device__ float g_bucket[EE];

// ---------------- CSR construction -----------------------------------------
__global__ void zero_kernel() {
    int i = blockIdx.x * blockDim.x + threadIdx.x;
    if (i < NN) { g_cnt[i] = 0; g_pos[i] = 0; }
}

__global__ void count_kernel(const int* __restrict__ idxs) {
    int e = blockIdx.x * blockDim.x + threadIdx.x;
    if (e < EE) atomicAdd(&g_cnt[idxs[e]], 1);
}

__global__ void scan_kernel() {
    __shared__ int buf[1024];
    __shared__ int carry;
    int tid = threadIdx.x;
    if (tid == 0) carry = 0;
    __syncthreads();
    for (int base = 0; base < NN; base += 1024) {
        int i = base + tid;
        int v = (i < NN) ? g_cnt[i] : 0;
        buf[tid] = v;
        __syncthreads();
        for (int off = 1; off < 1024; off <<= 1) {
            int t = (tid >= off) ? buf[tid - off] : 0;
            __syncthreads();
            buf[tid] += t;
            __syncthreads();
        }
        if (i < NN) g_offs[i] = carry + buf[tid] - v;   // exclusive
        __syncthreads();
        if (tid == 0) carry += buf[1023];
        __syncthreads();
    }
}

__global__ void fill_kernel(const int* __restrict__ idxs,
                            const float* __restrict__ ea) {
    int e = blockIdx.x * blockDim.x + threadIdx.x;
    if (e < EE) {
        int s = idxs[e];
        int p = atomicAdd(&g_pos[s], 1);
        g_bucket[g_offs[s] + p] = ea[e];
    }
}

// ---------------- weight-fold: W[128,Nc=128] = A[128,Kd] @ B[Kd,128] --------
// block 128 (i==128) computes bf[j] = avec @ B.
__global__ void fold_k(const float* __restrict__ A, const float* __restrict__ avec,
                       int Kd, const float* __restrict__ B, int ldb,
                       float* __restrict__ W, int ldw, float* __restrict__ bf) {
    int i = blockIdx.x;
    int j = threadIdx.x;
    const float* arow = (i < 128) ? (A + (size_t)i * Kd) : avec;
    float s = 0.f;
    #pragma unroll 4
    for (int k = 0; k < Kd; k++)
        s = fmaf(__ldg(&arow[k]), B[(size_t)k * ldb + j], s);
    if (i < 128) W[(size_t)i * ldw + j] = s;
    else         bf[j] = s;
}

// ---------------- double-buffered SGEMM -------------------------------------
// C[M, Ntot] = A[M,K] @ concat_N(B1, B2) (+bias)(+cnt?cbias)(+addend)(relu)
template<int BM, int BN, int BK, int TM, int TN, bool RELU>
__global__ void __launch_bounds__(256)
gemm_k(const float* __restrict__ A, int lda,
       const float* __restrict__ B1, const float* __restrict__ B2,
       int n1, int ldb, int K,
       float* __restrict__ C, int ldc, int M,
       const float* __restrict__ bias,
       const float* __restrict__ cbias, const int* __restrict__ cnt,
       const float* __restrict__ addend, int addld) {
    constexpr int THREADS = 256;
    constexpr int KQ  = BK / 4;                  // float4 per A-row chunk
    constexpr int NA  = (BM * KQ) / THREADS;     // A float4 loads / thread
    constexpr int NBq = (BK * (BN / 4)) / THREADS;
    constexpr int BMP = BM + 4;                  // pad, keeps 16B row alignment

    __shared__ float As[2][BK][BMP];
    __shared__ float Bs[2][BK][BN];

    int bm = blockIdx.y * BM;
    int bn = blockIdx.x * BN;
    const float* Bp = B1;
    int bcol = bn;
    if (B2 != nullptr && bn >= n1) { Bp = B2; bcol = bn - n1; }

    int tid = threadIdx.x;
    int tx = tid % (BN / TN);
    int ty = tid / (BN / TN);

    float4 ra[NA], rb[NBq];

    auto fetch = [&](int k0) {
        #pragma unroll
        for (int u = 0; u < NA; u++) {
            int t = tid + u * THREADS;
            int m = t / KQ, kq = t % KQ;
            int gm = bm + m;
            if (gm < M) ra[u] = *(const float4*)(A + (size_t)gm * lda + k0 + kq * 4);
            else        ra[u] = float4{0.f, 0.f, 0.f, 0.f};
        }
        #pragma unroll
        for (int u = 0; u < NBq; u++) {
            int t = tid + u * THREADS;
            int k = t / (BN / 4), nq = t % (BN / 4);
            rb[u] = *(const float4*)(Bp + (size_t)(k0 + k) * ldb + bcol + nq * 4);
        }
    };
    auto store = [&](int buf) {
        #pragma unroll
        for (int u = 0; u < NA; u++) {
            int t = tid + u * THREADS;
            int m = t / KQ, kq = t % KQ;
            As[buf][kq * 4 + 0][m] = ra[u].x;
            As[buf][kq * 4 + 1][m] = ra[u].y;
            As[buf][kq * 4 + 2][m] = ra[u].z;
            As[buf][kq * 4 + 3][m] = ra[u].w;
        }
        #pragma unroll
        for (int u = 0; u < NBq; u++) {
            int t = tid + u * THREADS;
            int k = t / (BN / 4), nq = t % (BN / 4);
            *(float4*)&Bs[buf][k][nq * 4] = rb[u];
        }
    };

    float acc[TM][TN] = {};

    fetch(0);
    store(0);
    __syncthreads();
    int nT = K / BK;
    for (int t = 0; t < nT; t++) {
        int cur = t & 1;
        if (t + 1 < nT) fetch((t + 1) * BK);
        #pragma unroll
        for (int k = 0; k < BK; k++) {
            float a[TM], b[TN];
            #pragma unroll
            for (int i = 0; i < TM; i += 4)
                *(float4*)&a[i] = *(const float4*)&As[cur][k][ty * TM + i];
            #pragma unroll
            for (int j = 0; j < TN; j += 4)
                *(float4*)&b[j] = *(const float4*)&Bs[cur][k][tx * TN + j];
            #pragma unroll
            for (int i = 0; i < TM; i++)
                #pragma unroll
                for (int j = 0; j < TN; j++)
                    acc[i][j] = fmaf(a[i], b[j], acc[i][j]);
        }
        if (t + 1 < nT) store(cur ^ 1);
        __syncthreads();
    }

    // epilogue
    #pragma unroll
    for (int i = 0; i < TM; i++) {
        int gm = bm + ty * TM + i;
        if (gm >= M) continue;
        bool cb = (cbias != nullptr) && (cnt[gm] > 0);
        #pragma unroll
        for (int j = 0; j < TN; j += 4) {
            int gn = bn + tx * TN + j;
            float4 v;
            v.x = acc[i][j + 0]; v.y = acc[i][j + 1];
            v.z = acc[i][j + 2]; v.w = acc[i][j + 3];
            if (bias != nullptr) {
                float4 bv = *(const float4*)(bias + gn);
                v.x += bv.x; v.y += bv.y; v.z += bv.z; v.w += bv.w;
            }
            if (cb) {
                float4 cv = *(const float4*)(cbias + gn);
                v.x += cv.x; v.y += cv.y; v.z += cv.z; v.w += cv.w;
            }
            if (addend != nullptr) {
                float4 av = *(const float4*)(addend + (size_t)gm * addld + gn);
                v.x += av.x; v.y += av.y; v.z += av.z; v.w += av.w;
            }
            if (RELU) {
                v.x = fmaxf(v.x, 0.f); v.y = fmaxf(v.y, 0.f);
                v.z = fmaxf(v.z, 0.f); v.w = fmaxf(v.w, 0.f);
            }
            *(float4*)(C + (size_t)gm * ldc + gn) = v;
        }
    }
}

// ---------------- per-node edge aggregation --------------------------------
// hbar[m,j] = mean over incident edges of relu(xw[m,j] + b[j] + a_e * we[j])
__global__ void edge_agg(const float* __restrict__ xw, int ld,
                         const float* __restrict__ we,
                         const float* __restrict__ b,
                         float* __restrict__ hbar) {
    __shared__ float sa[128];
    int m = blockIdx.x;
    int j = threadIdx.x;              // 0..127
    int deg = g_cnt[m];
    int start = g_offs[m];
    float xj = xw[(size_t)m * ld + j] + b[j];
    float wj = we[j];
    float s = 0.f;
    for (int base = 0; base < deg; base += 128) {
        int c = min(128, deg - base);
        if (j < c) sa[j] = g_bucket[start + base + j];
        __syncthreads();
        for (int t = 0; t < c; t++)
            s += fmaxf(fmaf(sa[t], wj, xj), 0.f);
        __syncthreads();
    }
    hbar[(size_t)m * HH + j] = deg ? s / (float)deg : 0.f;
}

// ---------------- final projection [N,128] @ [128,2] + b -------------------
__global__ void proj_kernel(const float* __restrict__ hidden,
                            const float* __restrict__ W,   // [128,2]
                            const float* __restrict__ b,
                            float* __restrict__ proj) {
    int gt = blockIdx.x * blockDim.x + threadIdx.x;
    int warp = gt >> 5;
    int lane = gt & 31;
    if (warp >= NN) return;
    float s0 = 0.f, s1 = 0.f;
    for (int j = lane; j < 128; j += 32) {
        float hv = hidden[warp * HH + j];
        s0 = fmaf(hv, W[j * 2 + 0], s0);
        s1 = fmaf(hv, W[j * 2 + 1], s1);
    }
    #pragma unroll
    for (int o = 16; o > 0; o >>= 1) {
        s0 += __shfl_down_sync(0xFFFFFFFFu, s0, o);
        s1 += __shfl_down_sync(0xFFFFFFFFu, s1, o);
    }
    if (lane == 0) {
        proj[warp * 2 + 0] = s0 + b[0];
        proj[warp * 2 + 1] = s1 + b[1];
    }
}

// ---------------- pairwise squared distances -------------------------------
__global__ void dist_kernel(const float* __restrict__ proj,
                            const int* __restrict__ idxs,
                            float* __restrict__ out) {
    int i = blockIdx.x * blockDim.x + threadIdx.x;
    if (i >= EE) return;
    int n  = i / (KK - 1);
    int nb = idxs[i];
    float dx = proj[n * 2 + 0] - proj[nb * 2 + 0];
    float dy = proj[n * 2 + 1] - proj[nb * 2 + 1];
    out[i] = dx * dx + dy * dy;
}

// ---------------- launch ---------------------------------------------------
extern "C" void kernel_launch(void* const* d_in, const int* in_sizes, int n_in,
                              void* d_out, int out_size) {
    const float* x     = (const float*)d_in[0];
    const float* ea    = (const float*)d_in[1];
    const int*   idxs  = (const int*)  d_in[2];
    const float* l1mw1 = (const float*)d_in[3];   // [785,128]
    const float* l1mb1 = (const float*)d_in[4];
    const float* l1mw2 = (const float*)d_in[5];   // [128,784]
    const float* l1mb2 = (const float*)d_in[6];
    const float* l1nw1 = (const float*)d_in[7];   // [1568,128]
    const float* l1nb1 = (const float*)d_in[8];
    const float* l1nw2 = (const float*)d_in[9];   // [128,128]
    const float* l1nb2 = (const float*)d_in[10];
    const float* l2mw1 = (const float*)d_in[11];  // [129,128]
    const float* l2mb1 = (const float*)d_in[12];
    const float* l2mw2 = (const float*)d_in[13];  // [128,128]
    const float* l2mb2 = (const float*)d_in[14];
    const float* l2nw1 = (const float*)d_in[15];  // [256,128]
    const float* l2nb1 = (const float*)d_in[16];
    const float* l2nw2 = (const float*)d_in[17];  // [128,2]
    const float* l2nb2 = (const float*)d_in[18];
    float* out = (float*)d_out;

    float *XW, *HW2, *hbar, *hidden, *proj, *Wf1, *Wf2, *Wh, *bf1, *bf2, *bh;
    int *cnt;
    cudaGetSymbolAddress((void**)&XW,     g_XW);
    cudaGetSymbolAddress((void**)&HW2,    g_HW2);
    cudaGetSymbolAddress((void**)&hbar,   g_hbar);
    cudaGetSymbolAddress((void**)&hidden, g_hidden);
    cudaGetSymbolAddress((void**)&proj,   g_proj);
    cudaGetSymbolAddress((void**)&Wf1,    g_Wf1);
    cudaGetSymbolAddress((void**)&Wf2,    g_Wf2);
    cudaGetSymbolAddress((void**)&Wh,     g_Wh);
    cudaGetSymbolAddress((void**)&bf1,    g_bf1);
    cudaGetSymbolAddress((void**)&bf2,    g_bf2);
    cudaGetSymbolAddress((void**)&bh,     g_bh);
    cudaGetSymbolAddress((void**)&cnt,    g_cnt);

    // ---- CSR over src = idxs.flatten() ----
    zero_kernel <<<(NN + 255) / 256, 256>>>();
    count_kernel<<<(EE + 255) / 256, 256>>>(idxs);
    scan_kernel <<<1, 1024>>>();
    fill_kernel <<<(EE + 255) / 256, 256>>>(idxs, ea);

    // ---- weight folds (tiny) ----
    // Wf1 = l1_msg_w2 @ W1b(l1 node),  bf1 = l1_msg_b2 @ W1b
    fold_k<<<129, 128>>>(l1mw2, l1mb2, DD, l1nw1 + (size_t)DD * HH, HH, Wf1, HH, bf1);
    // Wf2 = l2_msg_w2 @ W1b(l2 node),  bf2 = l2_msg_b2 @ W1b
    fold_k<<<129, 128>>>(l2mw2, l2mb2, HH, l2nw1 + (size_t)HH * HH, HH, Wf2, HH, bf2);
    // Wh = l1_node_w2 @ [l2 W1x_msg | l2 W1a_node],  bh = l1_node_b2 @ same
    fold_k<<<129, 128>>>(l1nw2, l1nb2, HH, l2mw1, HH, Wh,       256, bh);
    fold_k<<<129, 128>>>(l1nw2, l1nb2, HH, l2nw1, HH, Wh + 128, 256, bh + 128);

    // ---- layer 1 ----
    // XW = x @ [W1x_msg | W1a_node]      [N,256]
    gemm_k<128,128,16,8,8,false><<<dim3(2, 79), 256>>>(
        x, DD, l1mw1, l1nw1, 128, HH, DD,
        XW, 256, NN, nullptr, nullptr, nullptr, nullptr, 0);
    // hbar = mean_e relu(XW[:, :128][src] + a*we1 + b1)
    edge_agg<<<NN, HH>>>(XW, 256, l1mw1 + (size_t)DD * HH, l1mb1, hbar);
    // hidden = relu(hbar@Wf1 + XW[:,128:] + l1nb1 + [cnt>0]*bf1)
    gemm_k<64,128,16,4,8,true><<<dim3(1, 157), 256>>>(
        hbar, HH, Wf1, nullptr, HH, HH, HH,
        hidden, HH, NN, l1nb1, bf1, cnt, XW + 128, 256);

    // ---- layer 2 (h folded away) ----
    // HW2 = hidden @ Wh + bh             [N,256]
    gemm_k<128,128,16,8,8,false><<<dim3(2, 79), 256>>>(
        hidden, HH, Wh, nullptr, 256, 256, HH,
        HW2, 256, NN, bh, nullptr, nullptr, nullptr, 0);
    // hbar2 = mean_e relu(HW2[:, :128][src] + a*we2 + b1)
    edge_agg<<<NN, HH>>>(HW2, 256, l2mw1 + (size_t)HH * HH, l2mb1, hbar);
    // hidden2 = relu(hbar2@Wf2 + HW2[:,128:] + l2nb1 + [cnt>0]*bf2)
    gemm_k<64,128,16,4,8,true><<<dim3(1, 157), 256>>>(
        hbar, HH, Wf2, nullptr, HH, HH, HH,
        hidden, HH, NN, l2nb1, bf2, cnt, HW2 + 128, 256);

    // ---- output ----
    proj_kernel<<<(NN * 32 + 255) / 256, 256>>>(hidden, l2nw2, l2nb2, proj);
    dist_kernel<<<(EE + 255) / 256, 256>>>(proj, idxs, out);
}

// round 4
// speedup vs baseline: 2.4892x; 1.1168x over previous
#include <cuda_runtime.h>
#include <cuda_bf16.h>
#include <cstdint>

// Problem constants (fixed by the reference)
#define NN 10000          // nodes
#define DD 784            // input feat dim
#define KPAD 800          // DD padded to multiple of 32 (pad cols stay zero)
#define KK 16             // neighbors+1
#define EE (NN * (KK-1))  // edges = 150000
#define HH 128            // hidden width

// ============================ scratch globals ===============================
__device__ __align__(256) __nv_bfloat16 g_xh   [NN * KPAD];
__device__ __align__(256) __nv_bfloat16 g_xl   [NN * KPAD];
__device__ __align__(256) __nv_bfloat16 g_Wt1h [256 * KPAD]; // [l1 msgW1x^T ; l1 nodeW1a^T]
__device__ __align__(256) __nv_bfloat16 g_Wt1l [256 * KPAD];
__device__ __align__(256) __nv_bfloat16 g_Wf1h [HH * HH];    // (l1 msgW2 @ l1 nodeW1b)^T
__device__ __align__(256) __nv_bfloat16 g_Wf1l [HH * HH];
__device__ __align__(256) __nv_bfloat16 g_Wf2h [HH * HH];
__device__ __align__(256) __nv_bfloat16 g_Wf2l [HH * HH];
__device__ __align__(256) __nv_bfloat16 g_Whth [256 * HH];   // (l1 nodeW2 @ [l2 W1x | l2 W1a])^T
__device__ __align__(256) __nv_bfloat16 g_Whtl [256 * HH];
__device__ __align__(256) float g_bf1[HH];
__device__ __align__(256) float g_bf2[HH];
__device__ __align__(256) float g_bh [256];
__device__ __align__(256) float g_XW  [NN * 256];
__device__ __align__(256) float g_HW2 [NN * 256];
__device__ __align__(256) __nv_bfloat16 g_hbh [NN * HH];     // hbar hi/lo
__device__ __align__(256) __nv_bfloat16 g_hbl [NN * HH];
__device__ __align__(256) __nv_bfloat16 g_hidh[NN * HH];     // hidden hi/lo
__device__ __align__(256) __nv_bfloat16 g_hidl[NN * HH];
__device__ __align__(256) float g_hidden[NN * HH];           // layer-2 hidden (f32)
__device__ __align__(256) float g_proj[NN * 2];
__device__ int   g_cnt [NN];
__device__ int   g_offs[NN];
__device__ int   g_pos [NN];
__device__ int   g_counter;
__device__ __align__(256) float g_bucket[EE];

// ============================ small kernels =================================
__global__ void count_kernel(const int* __restrict__ idxs) {
    int e = blockIdx.x * blockDim.x + threadIdx.x;
    if (e < EE) atomicAdd(&g_cnt[idxs[e]], 1);
}

// offsets need only be disjoint ranges, not ordered -> block scan + atomic base
__global__ void offs_kernel() {
    __shared__ int sd[256];
    __shared__ int base_s;
    int t = threadIdx.x;
    int i = blockIdx.x * 256 + t;
    int v = (i < NN) ? g_cnt[i] : 0;
    sd[t] = v;
    __syncthreads();
    #pragma unroll
    for (int o = 1; o < 256; o <<= 1) {
        int x = (t >= o) ? sd[t - o] : 0;
        __syncthreads();
        sd[t] += x;
        __syncthreads();
    }
    if (t == 255) base_s = atomicAdd(&g_counter, sd[255]);
    __syncthreads();
    if (i < NN) g_offs[i] = base_s + sd[t] - v;
}

__global__ void fill_kernel(const int* __restrict__ idxs,
                            const float* __restrict__ ea) {
    int e = blockIdx.x * blockDim.x + threadIdx.x;
    if (e < EE) {
        int s = idxs[e];
        int p = atomicAdd(&g_pos[s], 1);
        g_bucket[g_offs[s] + p] = ea[e];
    }
}

// x[N,784] f32 -> bf16 hi/lo at row stride KPAD (pad cols stay zero)
__global__ void conv_split(const float* __restrict__ in,
                           __nv_bfloat16* __restrict__ hi,
                           __nv_bfloat16* __restrict__ lo) {
    int i = blockIdx.x * blockDim.x + threadIdx.x;
    if (i >= NN * (DD / 4)) return;
    int row = i / (DD / 4), c = i % (DD / 4);
    float4 v = ((const float4*)(in + (size_t)row * DD))[c];
    __nv_bfloat16 h0 = __float2bfloat16(v.x), h1 = __float2bfloat16(v.y);
    __nv_bfloat16 h2 = __float2bfloat16(v.z), h3 = __float2bfloat16(v.w);
    __nv_bfloat16 l0 = __float2bfloat16(v.x - __bfloat162float(h0));
    __nv_bfloat16 l1 = __float2bfloat16(v.y - __bfloat162float(h1));
    __nv_bfloat16 l2 = __float2bfloat16(v.z - __bfloat162float(h2));
    __nv_bfloat16 l3 = __float2bfloat16(v.w - __bfloat162float(h3));
    size_t o = (size_t)row * KPAD + c * 4;
    *(__nv_bfloat162*)(hi + o)     = __nv_bfloat162(h0, h1);
    *(__nv_bfloat162*)(hi + o + 2) = __nv_bfloat162(h2, h3);
    *(__nv_bfloat162*)(lo + o)     = __nv_bfloat162(l0, l1);
    *(__nv_bfloat162*)(lo + o + 2) = __nv_bfloat162(l2, l3);
}

// transpose+split: W[Kd][Nd] f32 -> out[(row_off+n)*ldout + k] bf16 hi/lo
__global__ void convT(const float* __restrict__ W, int Kd, int Nd,
                      __nv_bfloat16* __restrict__ oh, __nv_bfloat16* __restrict__ ol,
                      int row_off, int ldout) {
    int k = blockIdx.x * blockDim.x + threadIdx.x;
    int n = blockIdx.y;
    if (k >= Kd) return;
    float v = W[(size_t)k * Nd + n];
    __nv_bfloat16 h = __float2bfloat16(v);
    size_t o = (size_t)(row_off + n) * ldout + k;
    oh[o] = h;
    ol[o] = __float2bfloat16(v - __bfloat162float(h));
}

// weight fold: out^T[(row_off+j)*ldt + i] = A[i,:Kd] @ B[:,j]  (bf16 split).
// block i==128 computes bf[j] = avec @ B[:,j]  (f32)
__global__ void fold_k(const float* __restrict__ A, const float* __restrict__ avec,
                       int Kd, const float* __restrict__ B, int ldb,
                       __nv_bfloat16* __restrict__ oh, __nv_bfloat16* __restrict__ ol,
                       int row_off, int ldt, float* __restrict__ bf) {
    int i = blockIdx.x;
    int j = threadIdx.x;
    const float* arow = (i < 128) ? (A + (size_t)i * Kd) : avec;
    float s = 0.f;
    #pragma unroll 4
    for (int k = 0; k < Kd; k++)
        s = fmaf(__ldg(&arow[k]), B[(size_t)k * ldb + j], s);
    if (i < 128) {
        __nv_bfloat16 h = __float2bfloat16(s);
        size_t o = (size_t)(row_off + j) * ldt + i;
        oh[o] = h;
        ol[o] = __float2bfloat16(s - __bfloat162float(h));
    } else {
        bf[j] = s;
    }
}

// per-node edge aggregation: hbar[m,j] = mean_e relu(xw[m,j]+b[j]+a_e*we[j])
__global__ void edge_agg(const float* __restrict__ xw, int ld,
                         const float* __restrict__ we,
                         const float* __restrict__ b,
                         __nv_bfloat16* __restrict__ oh,
                         __nv_bfloat16* __restrict__ ol) {
    __shared__ float sa[128];
    int m = blockIdx.x;
    int j = threadIdx.x;
    int deg = g_cnt[m];
    int start = g_offs[m];
    float xj = xw[(size_t)m * ld + j] + b[j];
    float wj = we[j];
    float s = 0.f;
    for (int base = 0; base < deg; base += 128) {
        int c = min(128, deg - base);
        if (j < c) sa[j] = g_bucket[start + base + j];
        __syncthreads();
        for (int t = 0; t < c; t++)
            s += fmaxf(fmaf(sa[t], wj, xj), 0.f);
        __syncthreads();
    }
    float v = deg ? s / (float)deg : 0.f;
    __nv_bfloat16 h = __float2bfloat16(v);
    oh[(size_t)m * HH + j] = h;
    ol[(size_t)m * HH + j] = __float2bfloat16(v - __bfloat162float(h));
}

// ============================ mma.sync GEMM ================================
// C[M,Ntot] = (Ah+Al)[M,K] @ (Bh+Bl)^T  (B stored [Ntot][K]); 3-product split.
// Block tile 128x128, BK=32, 8 warps (2 M x 4 N), cp.async double buffer.
#define TPITCH 40                       // bf16 pitch (80 B) per smem tile row
#define TILE_B (128 * TPITCH * 2)      // 10240 B per tile
#define STAGE_B (4 * TILE_B)           // AH AL BH BL
#define GSMEM (2 * STAGE_B)            // 81920 B

__device__ __forceinline__ uint32_t smem_u32(const void* p) {
    uint32_t a;
    asm("{ .reg .u64 t; cvta.to.shared.u64 t, %1; cvt.u32.u64 %0, t; }"
        : "=r"(a) : "l"(p));
    return a;
}
__device__ __forceinline__ void cp16(uint32_t dst, const void* src, int sz) {
    asm volatile("cp.async.cg.shared.global [%0], [%1], 16, %2;"
        :: "r"(dst), "l"(src), "r"(sz) : "memory");
}
__device__ __forceinline__ void ldsm_x4(uint32_t* r, uint32_t a) {
    asm volatile("ldmatrix.sync.aligned.m8n8.x4.shared.b16 {%0,%1,%2,%3}, [%4];"
        : "=r"(r[0]), "=r"(r[1]), "=r"(r[2]), "=r"(r[3]) : "r"(a));
}
__device__ __forceinline__ void ldsm_x2(uint32_t* r, uint32_t a) {
    asm volatile("ldmatrix.sync.aligned.m8n8.x2.shared.b16 {%0,%1}, [%2];"
        : "=r"(r[0]), "=r"(r[1]) : "r"(a));
}
__device__ __forceinline__ void mma_bf16(float* c, const uint32_t* a, const uint32_t* b) {
    asm volatile("mma.sync.aligned.m16n8k16.row.col.f32.bf16.bf16.f32 "
        "{%0,%1,%2,%3}, {%4,%5,%6,%7}, {%8,%9}, {%0,%1,%2,%3};"
        : "+f"(c[0]), "+f"(c[1]), "+f"(c[2]), "+f"(c[3])
        : "r"(a[0]), "r"(a[1]), "r"(a[2]), "r"(a[3]), "r"(b[0]), "r"(b[1]));
}

__global__ void __launch_bounds__(256)
tgemm(const __nv_bfloat16* __restrict__ Ah, const __nv_bfloat16* __restrict__ Al,
      int lda,
      const __nv_bfloat16* __restrict__ Bh, const __nv_bfloat16* __restrict__ Bl,
      int ldb, int K, int M,
      float* __restrict__ C, int ldc,
      const float* __restrict__ bias,
      const float* __restrict__ cbias, const int* __restrict__ cnt,
      const float* __restrict__ addend, int addld, int relu,
      __nv_bfloat16* __restrict__ outHi, __nv_bfloat16* __restrict__ outLo) {
    extern __shared__ char smem[];
    uint32_t sb = smem_u32(smem);
    int tid = threadIdx.x;
    int wid = tid >> 5, lane = tid & 31;
    int bm = blockIdx.y * 128;
    int bn = blockIdx.x * 128;
    int wr = wid & 1;        // M warp (0..1), 64 rows each
    int wc = wid >> 1;       // N warp (0..3), 32 cols each

    const __nv_bfloat16* srcs[4] = {Ah, Al, Bh, Bl};

    auto issue = [&](int kc, int stg) {
        int k0 = kc * 32;
        #pragma unroll
        for (int u = 0; u < 8; u++) {
            int idx = tid + u * 256;         // 0..2047
            int tile = idx >> 9;             // 0..3
            int rem = idx & 511;
            int row = rem >> 2;              // 0..127
            int c   = rem & 3;               // 0..3 (16B chunks)
            int gr, maxr;
            if (tile < 2) { gr = bm + row; maxr = M; }
            else          { gr = bn + row; maxr = 1 << 30; }
            const __nv_bfloat16* s = srcs[tile] +
                (size_t)gr * ((tile < 2) ? lda : ldb) + k0 + c * 8;
            uint32_t d = sb + stg * STAGE_B + tile * TILE_B + row * (TPITCH * 2) + c * 16;
            cp16(d, s, (gr < maxr) ? 16 : 0);
        }
        asm volatile("cp.async.commit_group;" ::: "memory");
    };

    float acc[4][4][4] = {};
    int nT = K / 32;

    issue(0, 0);
    for (int t = 0; t < nT; t++) {
        int stg = t & 1;
        if (t + 1 < nT) {
            issue(t + 1, stg ^ 1);
            asm volatile("cp.async.wait_group 1;" ::: "memory");
        } else {
            asm volatile("cp.async.wait_group 0;" ::: "memory");
        }
        __syncthreads();

        uint32_t baseAH = sb + stg * STAGE_B + 0 * TILE_B;
        uint32_t baseAL = sb + stg * STAGE_B + 1 * TILE_B;
        uint32_t baseBH = sb + stg * STAGE_B + 2 * TILE_B;
        uint32_t baseBL = sb + stg * STAGE_B + 3 * TILE_B;

        #pragma unroll
        for (int ks = 0; ks < 2; ks++) {
            uint32_t aH[4][4], aL[4][4], bH[4][2], bL[4][2];
            int acol = (ks * 16 + (lane >> 4) * 8) * 2;
            int bcol = (ks * 16 + ((lane >> 3) & 1) * 8) * 2;
            #pragma unroll
            for (int mi = 0; mi < 4; mi++) {
                int arow = wr * 64 + mi * 16 + (lane & 15);
                ldsm_x4(aH[mi], baseAH + arow * (TPITCH * 2) + acol);
                ldsm_x4(aL[mi], baseAL + arow * (TPITCH * 2) + acol);
            }
            #pragma unroll
            for (int ni = 0; ni < 4; ni++) {
                int brow = wc * 32 + ni * 8 + (lane & 7);
                ldsm_x2(bH[ni], baseBH + brow * (TPITCH * 2) + bcol);
                ldsm_x2(bL[ni], baseBL + brow * (TPITCH * 2) + bcol);
            }
            #pragma unroll
            for (int mi = 0; mi < 4; mi++)
                #pragma unroll
                for (int ni = 0; ni < 4; ni++) {
                    mma_bf16(acc[mi][ni], aH[mi], bH[ni]);
                    mma_bf16(acc[mi][ni], aH[mi], bL[ni]);
                    mma_bf16(acc[mi][ni], aL[mi], bH[ni]);
                }
        }
        __syncthreads();
    }

    // epilogue: c frag mapping: r0,r1 -> row lane/4, cols (lane%4)*2+{0,1};
    //           r2,r3 -> row lane/4+8
    #pragma unroll
    for (int mi = 0; mi < 4; mi++) {
        #pragma unroll
        for (int half = 0; half < 2; half++) {
            int gm = bm + wr * 64 + mi * 16 + (lane >> 2) + half * 8;
            if (gm >= M) continue;
            bool cb = (cbias != nullptr) && (cnt[gm] > 0);
            #pragma unroll
            for (int ni = 0; ni < 4; ni++) {
                #pragma unroll
                for (int e = 0; e < 2; e++) {
                    int gn = bn + wc * 32 + ni * 8 + (lane & 3) * 2 + e;
                    float v = acc[mi][ni][half * 2 + e];
                    if (bias)   v += __ldg(&bias[gn]);
                    if (cb)     v += __ldg(&cbias[gn]);
                    if (addend) v += addend[(size_t)gm * addld + gn];
                    if (relu)   v = fmaxf(v, 0.f);
                    if (C) C[(size_t)gm * ldc + gn] = v;
                    if (outHi) {
                        __nv_bfloat16 h = __float2bfloat16(v);
                        outHi[(size_t)gm * 128 + gn] = h;
                        outLo[(size_t)gm * 128 + gn] =
                            __float2bfloat16(v - __bfloat162float(h));
                    }
                }
            }
        }
    }
}

// ---------------- final projection [N,128] @ [128,2] + b -------------------
__global__ void proj_kernel(const float* __restrict__ hidden,
                            const float* __restrict__ W,
                            const float* __restrict__ b,
                            float* __restrict__ proj) {
    int gt = blockIdx.x * blockDim.x + threadIdx.x;
    int warp = gt >> 5;
    int lane = gt & 31;
    if (warp >= NN) return;
    float s0 = 0.f, s1 = 0.f;
    for (int j = lane; j < 128; j += 32) {
        float hv = hidden[warp * HH + j];
        s0 = fmaf(hv, W[j * 2 + 0], s0);
        s1 = fmaf(hv, W[j * 2 + 1], s1);
    }
    #pragma unroll
    for (int o = 16; o > 0; o >>= 1) {
        s0 += __shfl_down_sync(0xFFFFFFFFu, s0, o);
        s1 += __shfl_down_sync(0xFFFFFFFFu, s1, o);
    }
    if (lane == 0) {
        proj[warp * 2 + 0] = s0 + b[0];
        proj[warp * 2 + 1] = s1 + b[1];
    }
}

// ---------------- pairwise squared distances -------------------------------
__global__ void dist_kernel(const float* __restrict__ proj,
                            const int* __restrict__ idxs,
                            float* __restrict__ out) {
    int i = blockIdx.x * blockDim.x + threadIdx.x;
    if (i >= EE) return;
    int n  = i / (KK - 1);
    int nb = idxs[i];
    float dx = proj[n * 2 + 0] - proj[nb * 2 + 0];
    float dy = proj[n * 2 + 1] - proj[nb * 2 + 1];
    out[i] = dx * dx + dy * dy;
}

// ============================ launch ========================================
extern "C" void kernel_launch(void* const* d_in, const int* in_sizes, int n_in,
                              void* d_out, int out_size) {
    const float* x     = (const float*)d_in[0];
    const float* ea    = (const float*)d_in[1];
    const int*   idxs  = (const int*)  d_in[2];
    const float* l1mw1 = (const float*)d_in[3];   // [785,128]
    const float* l1mb1 = (const float*)d_in[4];
    const float* l1mw2 = (const float*)d_in[5];   // [128,784]
    const float* l1mb2 = (const float*)d_in[6];
    const float* l1nw1 = (const float*)d_in[7];   // [1568,128]
    const float* l1nb1 = (const float*)d_in[8];
    const float* l1nw2 = (const float*)d_in[9];   // [128,128]
    const float* l1nb2 = (const float*)d_in[10];
    const float* l2mw1 = (const float*)d_in[11];  // [129,128]
    const float* l2mb1 = (const float*)d_in[12];
    const float* l2mw2 = (const float*)d_in[13];  // [128,128]
    const float* l2mb2 = (const float*)d_in[14];
    const float* l2nw1 = (const float*)d_in[15];  // [256,128]
    const float* l2nb1 = (const float*)d_in[16];
    const float* l2nw2 = (const float*)d_in[17];  // [128,2]
    const float* l2nb2 = (const float*)d_in[18];
    float* out = (float*)d_out;

    __nv_bfloat16 *xh, *xl, *Wt1h, *Wt1l, *Wf1h, *Wf1l, *Wf2h, *Wf2l, *Whth, *Whtl;
    __nv_bfloat16 *hbh, *hbl, *hidh, *hidl;
    float *XW, *HW2, *hidden, *proj, *bf1, *bf2, *bh;
    int *cnt, *pos, *counter;
    cudaGetSymbolAddress((void**)&xh,   g_xh);
    cudaGetSymbolAddress((void**)&xl,   g_xl);
    cudaGetSymbolAddress((void**)&Wt1h, g_Wt1h);
    cudaGetSymbolAddress((void**)&Wt1l, g_Wt1l);
    cudaGetSymbolAddress((void**)&Wf1h, g_Wf1h);
    cudaGetSymbolAddress((void**)&Wf1l, g_Wf1l);
    cudaGetSymbolAddress((void**)&Wf2h, g_Wf2h);
    cudaGetSymbolAddress((void**)&Wf2l, g_Wf2l);
    cudaGetSymbolAddress((void**)&Whth, g_Whth);
    cudaGetSymbolAddress((void**)&Whtl, g_Whtl);
    cudaGetSymbolAddress((void**)&hbh,  g_hbh);
    cudaGetSymbolAddress((void**)&hbl,  g_hbl);
    cudaGetSymbolAddress((void**)&hidh, g_hidh);
    cudaGetSymbolAddress((void**)&hidl, g_hidl);
    cudaGetSymbolAddress((void**)&XW,   g_XW);
    cudaGetSymbolAddress((void**)&HW2,  g_HW2);
    cudaGetSymbolAddress((void**)&hidden, g_hidden);
    cudaGetSymbolAddress((void**)&proj, g_proj);
    cudaGetSymbolAddress((void**)&bf1,  g_bf1);
    cudaGetSymbolAddress((void**)&bf2,  g_bf2);
    cudaGetSymbolAddress((void**)&bh,   g_bh);
    cudaGetSymbolAddress((void**)&cnt,  g_cnt);
    cudaGetSymbolAddress((void**)&pos,  g_pos);
    cudaGetSymbolAddress((void**)&counter, g_counter);

    cudaFuncSetAttribute(tgemm, cudaFuncAttributeMaxDynamicSharedMemorySize, GSMEM);

    // ---- CSR over src = idxs.flatten() (offsets unordered but disjoint) ----
    cudaMemsetAsync(cnt, 0, NN * sizeof(int));
    cudaMemsetAsync(pos, 0, NN * sizeof(int));
    cudaMemsetAsync(counter, 0, sizeof(int));
    count_kernel<<<(EE + 255) / 256, 256>>>(idxs);
    offs_kernel <<<(NN + 255) / 256, 256>>>();
    fill_kernel <<<(EE + 255) / 256, 256>>>(idxs, ea);

    // ---- operand prep ----
    conv_split<<<(NN * (DD / 4) + 255) / 256, 256>>>(x, xh, xl);
    convT<<<dim3((DD + 255) / 256, 128), 256>>>(l1mw1, DD, 128, Wt1h, Wt1l, 0,   KPAD);
    convT<<<dim3((DD + 255) / 256, 128), 256>>>(l1nw1, DD, 128, Wt1h, Wt1l, 128, KPAD);
    // Wf1 = l1_msg_w2 @ l1 node W1b ; bf1 = l1_msg_b2 @ W1b
    fold_k<<<129, 128>>>(l1mw2, l1mb2, DD, l1nw1 + (size_t)DD * HH, HH,
                         Wf1h, Wf1l, 0, HH, bf1);
    // Wf2 = l2_msg_w2 @ l2 node W1b ; bf2 = l2_msg_b2 @ W1b
    fold_k<<<129, 128>>>(l2mw2, l2mb2, HH, l2nw1 + (size_t)HH * HH, HH,
                         Wf2h, Wf2l, 0, HH, bf2);
    // Wh = l1_node_w2 @ [l2 W1x_msg | l2 W1a_node] ; bh likewise
    fold_k<<<129, 128>>>(l1nw2, l1nb2, HH, l2mw1, HH, Whth, Whtl, 0,   HH, bh);
    fold_k<<<129, 128>>>(l1nw2, l1nb2, HH, l2nw1, HH, Whth, Whtl, 128, HH, bh + 128);

    // ---- layer 1 ----
    // XW = x @ [W1x_msg | W1a_node]   [N,256]
    tgemm<<<dim3(2, 79), 256, GSMEM>>>(
        xh, xl, KPAD, Wt1h, Wt1l, KPAD, KPAD, NN,
        XW, 256, nullptr, nullptr, nullptr, nullptr, 0, 0,
        nullptr, nullptr);
    // hbar = mean_e relu(XW[:, :128][src] + a*we1 + b1)   (bf16 pair)
    edge_agg<<<NN, HH>>>(XW, 256, l1mw1 + (size_t)DD * HH, l1mb1, hbh, hbl);
    // hidden1 = relu(hbar@Wf1 + XW[:,128:] + l1nb1 + [cnt>0]*bf1) -> bf16 pair
    tgemm<<<dim3(1, 79), 256, GSMEM>>>(
        hbh, hbl, HH, Wf1h, Wf1l, HH, HH, NN,
        nullptr, 0, l1nb1, bf1, cnt, XW + 128, 256, 1,
        hidh, hidl);

    // ---- layer 2 (intermediate h folded away) ----
    // HW2 = hidden1 @ Wh + bh          [N,256]
    tgemm<<<dim3(2, 79), 256, GSMEM>>>(
        hidh, hidl, HH, Whth, Whtl, HH, HH, NN,
        HW2, 256, bh, nullptr, nullptr, nullptr, 0, 0,
        nullptr, nullptr);
    // hbar2 = mean_e relu(HW2[:, :128][src] + a*we2 + b1)
    edge_agg<<<NN, HH>>>(HW2, 256, l2mw1 + (size_t)HH * HH, l2mb1, hbh, hbl);
    // hidden2 = relu(hbar2@Wf2 + HW2[:,128:] + l2nb1 + [cnt>0]*bf2)  (f32)
    tgemm<<<dim3(1, 79), 256, GSMEM>>>(
        hbh, hbl, HH, Wf2h, Wf2l, HH, HH, NN,
        hidden, HH, l2nb1, bf2, cnt, HW2 + 128, 256, 1,
        nullptr, nullptr);

    // ---- output ----
    proj_kernel<<<(NN * 32 + 255) / 256, 256>>>(hidden, l2nw2, l2nb2, proj);
    dist_kernel<<<(EE + 255) / 256, 256>>>(proj, idxs, out);
}

// round 6
// speedup vs baseline: 3.6939x; 1.4839x over previous
#include <cuda_runtime.h>
#include <cuda_bf16.h>
#include <cstdint>

// Problem constants (fixed by the reference)
#define NN 10000          // nodes
#define DD 784            // input feat dim
#define KPAD 800          // DD padded to multiple of 32 (pad cols stay zero)
#define KK 16             // neighbors+1
#define EE (NN * (KK-1))  // edges = 150000
#define HH 128            // hidden width

// ============================ scratch globals ===============================
__device__ __align__(256) __nv_bfloat16 g_xh   [NN * KPAD];
__device__ __align__(256) __nv_bfloat16 g_xl   [NN * KPAD];
__device__ __align__(256) __nv_bfloat16 g_Wt1h [256 * KPAD]; // [l1 msgW1x^T ; l1 nodeW1a^T]
__device__ __align__(256) __nv_bfloat16 g_Wt1l [256 * KPAD];
__device__ __align__(256) __nv_bfloat16 g_Wf1h [HH * HH];    // (l1 msgW2 @ l1 nodeW1b)^T
__device__ __align__(256) __nv_bfloat16 g_Wf1l [HH * HH];
__device__ __align__(256) __nv_bfloat16 g_Wf2h [HH * HH];
__device__ __align__(256) __nv_bfloat16 g_Wf2l [HH * HH];
__device__ __align__(256) __nv_bfloat16 g_Whth [256 * HH];   // (l1 nodeW2 @ [l2 W1x | l2 W1a])^T
__device__ __align__(256) __nv_bfloat16 g_Whtl [256 * HH];
__device__ __align__(256) float g_bf1[HH];
__device__ __align__(256) float g_bf2[HH];
__device__ __align__(256) float g_bh [256];
__device__ __align__(256) float g_XW  [NN * 256];
__device__ __align__(256) float g_HW2 [NN * 256];
__device__ __align__(256) __nv_bfloat16 g_hbh [NN * HH];     // hbar hi/lo
__device__ __align__(256) __nv_bfloat16 g_hbl [NN * HH];
__device__ __align__(256) __nv_bfloat16 g_hidh[NN * HH];     // hidden hi/lo
__device__ __align__(256) __nv_bfloat16 g_hidl[NN * HH];
__device__ __align__(256) float g_hidden[NN * HH];           // layer-2 hidden (f32)
__device__ __align__(256) float g_proj[NN * 2];
__device__ int   g_cnt [NN];
__device__ int   g_offs[NN];
__device__ int   g_pos [NN];
__device__ int   g_counter;
__device__ __align__(256) float g_bucket[EE];

// ============================ small kernels =================================
__global__ void count_kernel(const int* __restrict__ idxs) {
    int e = blockIdx.x * blockDim.x + threadIdx.x;
    if (e < EE) atomicAdd(&g_cnt[idxs[e]], 1);
}

// offsets need only be disjoint ranges, not ordered -> block scan + atomic base
__global__ void offs_kernel() {
    __shared__ int sd[256];
    __shared__ int base_s;
    int t = threadIdx.x;
    int i = blockIdx.x * 256 + t;
    int v = (i < NN) ? g_cnt[i] : 0;
    sd[t] = v;
    __syncthreads();
    #pragma unroll
    for (int o = 1; o < 256; o <<= 1) {
        int x = (t >= o) ? sd[t - o] : 0;
        __syncthreads();
        sd[t] += x;
        __syncthreads();
    }
    if (t == 255) base_s = atomicAdd(&g_counter, sd[255]);
    __syncthreads();
    if (i < NN) g_offs[i] = base_s + sd[t] - v;
}

__global__ void fill_kernel(const int* __restrict__ idxs,
                            const float* __restrict__ ea) {
    int e = blockIdx.x * blockDim.x + threadIdx.x;
    if (e < EE) {
        int s = idxs[e];
        int p = atomicAdd(&g_pos[s], 1);
        g_bucket[g_offs[s] + p] = ea[e];
    }
}

// x[N,784] f32 -> bf16 hi/lo at row stride KPAD (pad cols stay zero)
__global__ void conv_split(const float* __restrict__ in,
                           __nv_bfloat16* __restrict__ hi,
                           __nv_bfloat16* __restrict__ lo) {
    int i = blockIdx.x * blockDim.x + threadIdx.x;
    if (i >= NN * (DD / 4)) return;
    int row = i / (DD / 4), c = i % (DD / 4);
    float4 v = ((const float4*)(in + (size_t)row * DD))[c];
    __nv_bfloat16 h0 = __float2bfloat16(v.x), h1 = __float2bfloat16(v.y);
    __nv_bfloat16 h2 = __float2bfloat16(v.z), h3 = __float2bfloat16(v.w);
    __nv_bfloat16 l0 = __float2bfloat16(v.x - __bfloat162float(h0));
    __nv_bfloat16 l1 = __float2bfloat16(v.y - __bfloat162float(h1));
    __nv_bfloat16 l2 = __float2bfloat16(v.z - __bfloat162float(h2));
    __nv_bfloat16 l3 = __float2bfloat16(v.w - __bfloat162float(h3));
    size_t o = (size_t)row * KPAD + c * 4;
    *(__nv_bfloat162*)(hi + o)     = __nv_bfloat162(h0, h1);
    *(__nv_bfloat162*)(hi + o + 2) = __nv_bfloat162(h2, h3);
    *(__nv_bfloat162*)(lo + o)     = __nv_bfloat162(l0, l1);
    *(__nv_bfloat162*)(lo + o + 2) = __nv_bfloat162(l2, l3);
}

// transpose+split: W[Kd][Nd] f32 -> out[(row_off+n)*ldout + k] bf16 hi/lo
__global__ void convT(const float* __restrict__ W, int Kd, int Nd,
                      __nv_bfloat16* __restrict__ oh, __nv_bfloat16* __restrict__ ol,
                      int row_off, int ldout) {
    int k = blockIdx.x * blockDim.x + threadIdx.x;
    int n = blockIdx.y;
    if (k >= Kd) return;
    float v = W[(size_t)k * Nd + n];
    __nv_bfloat16 h = __float2bfloat16(v);
    size_t o = (size_t)(row_off + n) * ldout + k;
    oh[o] = h;
    ol[o] = __float2bfloat16(v - __bfloat162float(h));
}

// weight fold: out^T[(row_off+j)*ldt + i] = A[i,:Kd] @ B[:,j]  (bf16 split).
// block i==128 computes bf[j] = avec @ B[:,j] (f32). K parallelized over y.
__global__ void fold_k(const float* __restrict__ A, const float* __restrict__ avec,
                       int Kd, const float* __restrict__ B, int ldb,
                       __nv_bfloat16* __restrict__ oh, __nv_bfloat16* __restrict__ ol,
                       int row_off, int ldt, float* __restrict__ bf) {
    __shared__ float red[4][128];
    int i = blockIdx.x;
    int j = threadIdx.x;
    int kq = threadIdx.y;            // 0..3
    const float* arow = (i < 128) ? (A + (size_t)i * Kd) : avec;
    int chunk = (Kd + 3) >> 2;
    int k0 = kq * chunk, k1 = min(Kd, k0 + chunk);
    float s = 0.f;
    #pragma unroll 4
    for (int k = k0; k < k1; k++)
        s = fmaf(__ldg(&arow[k]), B[(size_t)k * ldb + j], s);
    red[kq][j] = s;
    __syncthreads();
    if (kq == 0) {
        s = red[0][j] + red[1][j] + red[2][j] + red[3][j];
        if (i < 128) {
            __nv_bfloat16 h = __float2bfloat16(s);
            size_t o = (size_t)(row_off + j) * ldt + i;
            oh[o] = h;
            ol[o] = __float2bfloat16(s - __bfloat162float(h));
        } else {
            bf[j] = s;
        }
    }
}

// per-node edge aggregation: hbar[m,j] = mean_e relu(xw[m,j]+b[j]+a_e*we[j])
__global__ void edge_agg(const float* __restrict__ xw, int ld,
                         const float* __restrict__ we,
                         const float* __restrict__ b,
                         __nv_bfloat16* __restrict__ oh,
                         __nv_bfloat16* __restrict__ ol) {
    __shared__ float sa[128];
    int m = blockIdx.x;
    int j = threadIdx.x;
    int deg = g_cnt[m];
    int start = g_offs[m];
    float xj = xw[(size_t)m * ld + j] + b[j];
    float wj = we[j];
    float s = 0.f;
    for (int base = 0; base < deg; base += 128) {
        int c = min(128, deg - base);
        if (j < c) sa[j] = g_bucket[start + base + j];
        __syncthreads();
        for (int t = 0; t < c; t++)
            s += fmaxf(fmaf(sa[t], wj, xj), 0.f);
        __syncthreads();
    }
    float v = deg ? s / (float)deg : 0.f;
    __nv_bfloat16 h = __float2bfloat16(v);
    oh[(size_t)m * HH + j] = h;
    ol[(size_t)m * HH + j] = __float2bfloat16(v - __bfloat162float(h));
}

// ============================ mma.sync GEMM ================================
// C[M,Ntot] = (Ah+Al)[M,K] @ (Bh+Bl)^T (B stored [Ntot][K]); 3-product split.
// Block tile 64x128, BK=32, 8 warps (2 M x 4 N, warp tile 32x32),
// 3-stage cp.async pipeline.
#define TPITCH 40                      // bf16 pitch (80 B) per smem tile row
#define TILE_A (64 * TPITCH * 2)       // 5120 B
#define TILE_B (128 * TPITCH * 2)      // 10240 B
#define STAGE_B (2 * TILE_A + 2 * TILE_B)   // 30720 B: AH AL BH BL
#define GSMEM (3 * STAGE_B)            // 92160 B

__device__ __forceinline__ uint32_t smem_u32(const void* p) {
    uint32_t a;
    asm("{ .reg .u64 t; cvta.to.shared.u64 t, %1; cvt.u32.u64 %0, t; }"
        : "=r"(a) : "l"(p));
    return a;
}
__device__ __forceinline__ void cp16(uint32_t dst, const void* src, int sz) {
    asm volatile("cp.async.cg.shared.global [%0], [%1], 16, %2;"
        :: "r"(dst), "l"(src), "r"(sz) : "memory");
}
__device__ __forceinline__ void ldsm_x4(uint32_t* r, uint32_t a) {
    asm volatile("ldmatrix.sync.aligned.m8n8.x4.shared.b16 {%0,%1,%2,%3}, [%4];"
        : "=r"(r[0]), "=r"(r[1]), "=r"(r[2]), "=r"(r[3]) : "r"(a));
}
__device__ __forceinline__ void ldsm_x2(uint32_t* r, uint32_t a) {
    asm volatile("ldmatrix.sync.aligned.m8n8.x2.shared.b16 {%0,%1}, [%2];"
        : "=r"(r[0]), "=r"(r[1]) : "r"(a));
}
__device__ __forceinline__ void mma_bf16(float* c, const uint32_t* a, const uint32_t* b) {
    asm volatile("mma.sync.aligned.m16n8k16.row.col.f32.bf16.bf16.f32 "
        "{%0,%1,%2,%3}, {%4,%5,%6,%7}, {%8,%9}, {%0,%1,%2,%3};"
        : "+f"(c[0]), "+f"(c[1]), "+f"(c[2]), "+f"(c[3])
        : "r"(a[0]), "r"(a[1]), "r"(a[2]), "r"(a[3]), "r"(b[0]), "r"(b[1]));
}

__global__ void __launch_bounds__(256)
tgemm(const __nv_bfloat16* __restrict__ Ah, const __nv_bfloat16* __restrict__ Al,
      int lda,
      const __nv_bfloat16* __restrict__ Bh, const __nv_bfloat16* __restrict__ Bl,
      int ldb, int K, int M,
      float* __restrict__ C, int ldc,
      const float* __restrict__ bias,
      const float* __restrict__ cbias, const int* __restrict__ cnt,
      const float* __restrict__ addend, int addld, int relu,
      __nv_bfloat16* __restrict__ outHi, __nv_bfloat16* __restrict__ outLo) {
    extern __shared__ char smem[];
    uint32_t sb = smem_u32(smem);
    int tid = threadIdx.x;
    int wid = tid >> 5, lane = tid & 31;
    int bm = blockIdx.y * 64;
    int bn = blockIdx.x * 128;
    int wr = wid & 1;        // M warp (0..1), 32 rows each
    int wc = wid >> 1;       // N warp (0..3), 32 cols each

    const __nv_bfloat16* srcs[4] = {Ah, Al, Bh, Bl};
    const int toff[4] = {0, TILE_A, 2 * TILE_A, 2 * TILE_A + TILE_B};

    // per stage: AH 64 rows, AL 64 rows, BH 128 rows, BL 128 rows; 4 x16B/row
    auto issue = [&](int kc, int stg) {
        int k0 = kc * 32;
        #pragma unroll
        for (int u = 0; u < 6; u++) {
            int idx = tid + u * 256;          // 0..1535
            int tile, row;
            if (idx < 512) { tile = idx >> 8; row = (idx & 255) >> 2; }
            else { tile = 2 + ((idx - 512) >> 9); row = ((idx - 512) & 511) >> 2; }
            int c = idx & 3;
            int gr, maxr;
            if (tile < 2) { gr = bm + row; maxr = M; }
            else          { gr = bn + row; maxr = 1 << 30; }
            const __nv_bfloat16* s = srcs[tile] +
                (size_t)gr * ((tile < 2) ? lda : ldb) + k0 + c * 8;
            uint32_t d = sb + stg * STAGE_B + toff[tile] + row * (TPITCH * 2) + c * 16;
            cp16(d, s, (gr < maxr) ? 16 : 0);
        }
        asm volatile("cp.async.commit_group;" ::: "memory");
    };

    float acc[2][4][4] = {};
    int nT = K / 32;

    issue(0, 0);
    if (nT > 1) issue(1, 1);
    for (int t = 0; t < nT; t++) {
        int stg = t % 3;
        if (t + 2 < nT) {
            issue(t + 2, (t + 2) % 3);       // buffer freed at end of iter t-1
            asm volatile("cp.async.wait_group 2;" ::: "memory");
        } else if (t + 1 < nT) {
            asm volatile("cp.async.wait_group 1;" ::: "memory");
        } else {
            asm volatile("cp.async.wait_group 0;" ::: "memory");
        }
        __syncthreads();

        uint32_t baseAH = sb + stg * STAGE_B + toff[0];
        uint32_t baseAL = sb + stg * STAGE_B + toff[1];
        uint32_t baseBH = sb + stg * STAGE_B + toff[2];
        uint32_t baseBL = sb + stg * STAGE_B + toff[3];

        #pragma unroll
        for (int ks = 0; ks < 2; ks++) {
            uint32_t aH[2][4], aL[2][4], bH[4][2], bL[4][2];
            int acol = (ks * 16 + (lane >> 4) * 8) * 2;
            int bcol = (ks * 16 + ((lane >> 3) & 1) * 8) * 2;
            #pragma unroll
            for (int mi = 0; mi < 2; mi++) {
                int arow = wr * 32 + mi * 16 + (lane & 15);
                ldsm_x4(aH[mi], baseAH + arow * (TPITCH * 2) + acol);
                ldsm_x4(aL[mi], baseAL + arow * (TPITCH * 2) + acol);
            }
            #pragma unroll
            for (int ni = 0; ni < 4; ni++) {
                int brow = wc * 32 + ni * 8 + (lane & 7);
                ldsm_x2(bH[ni], baseBH + brow * (TPITCH * 2) + bcol);
                ldsm_x2(bL[ni], baseBL + brow * (TPITCH * 2) + bcol);
            }
            #pragma unroll
            for (int mi = 0; mi < 2; mi++)
                #pragma unroll
                for (int ni = 0; ni < 4; ni++) {
                    mma_bf16(acc[mi][ni], aH[mi], bH[ni]);
                    mma_bf16(acc[mi][ni], aH[mi], bL[ni]);
                    mma_bf16(acc[mi][ni], aL[mi], bH[ni]);
                }
        }
        __syncthreads();
    }

    // epilogue: c frag: r0,r1 -> row lane/4, cols (lane%4)*2+{0,1}; r2,r3 -> +8
    #pragma unroll
    for (int mi = 0; mi < 2; mi++) {
        #pragma unroll
        for (int half = 0; half < 2; half++) {
            int gm = bm + wr * 32 + mi * 16 + (lane >> 2) + half * 8;
            if (gm >= M) continue;
            bool cb = (cbias != nullptr) && (cnt[gm] > 0);
            #pragma unroll
            for (int ni = 0; ni < 4; ni++) {
                #pragma unroll
                for (int e = 0; e < 2; e++) {
                    int gn = bn + wc * 32 + ni * 8 + (lane & 3) * 2 + e;
                    float v = acc[mi][ni][half * 2 + e];
                    if (bias)   v += __ldg(&bias[gn]);
                    if (cb)     v += __ldg(&cbias[gn]);
                    if (addend) v += addend[(size_t)gm * addld + gn];
                    if (relu)   v = fmaxf(v, 0.f);
                    if (C) C[(size_t)gm * ldc + gn] = v;
                    if (outHi) {
                        __nv_bfloat16 h = __float2bfloat16(v);
                        outHi[(size_t)gm * 128 + gn] = h;
                        outLo[(size_t)gm * 128 + gn] =
                            __float2bfloat16(v - __bfloat162float(h));
                    }
                }
            }
        }
    }
}

// ---------------- final projection [N,128] @ [128,2] + b -------------------
__global__ void proj_kernel(const float* __restrict__ hidden,
                            const float* __restrict__ W,
                            const float* __restrict__ b,
                            float* __restrict__ proj) {
    int gt = blockIdx.x * blockDim.x + threadIdx.x;
    int warp = gt >> 5;
    int lane = gt & 31;
    if (warp >= NN) return;
    float s0 = 0.f, s1 = 0.f;
    for (int j = lane; j < 128; j += 32) {
        float hv = hidden[warp * HH + j];
        s0 = fmaf(hv, W[j * 2 + 0], s0);
        s1 = fmaf(hv, W[j * 2 + 1], s1);
    }
    #pragma unroll
    for (int o = 16; o > 0; o >>= 1) {
        s0 += __shfl_down_sync(0xFFFFFFFFu, s0, o);
        s1 += __shfl_down_sync(0xFFFFFFFFu, s1, o);
    }
    if (lane == 0) {
        proj[warp * 2 + 0] = s0 + b[0];
        proj[warp * 2 + 1] = s1 + b[1];
    }
}

// ---------------- pairwise squared distances -------------------------------
__global__ void dist_kernel(const float* __restrict__ proj,
                            const int* __restrict__ idxs,
                            float* __restrict__ out) {
    int i = blockIdx.x * blockDim.x + threadIdx.x;
    if (i >= EE) return;
    int n  = i / (KK - 1);
    int nb = idxs[i];
    float dx = proj[n * 2 + 0] - proj[nb * 2 + 0];
    float dy = proj[n * 2 + 1] - proj[nb * 2 + 1];
    out[i] = dx * dx + dy * dy;
}

// ============================ launch ========================================
extern "C" void kernel_launch(void* const* d_in, const int* in_sizes, int n_in,
                              void* d_out, int out_size) {
    const float* x     = (const float*)d_in[0];
    const float* ea    = (const float*)d_in[1];
    const int*   idxs  = (const int*)  d_in[2];
    const float* l1mw1 = (const float*)d_in[3];   // [785,128]
    const float* l1mb1 = (const float*)d_in[4];
    const float* l1mw2 = (const float*)d_in[5];   // [128,784]
    const float* l1mb2 = (const float*)d_in[6];
    const float* l1nw1 = (const float*)d_in[7];   // [1568,128]
    const float* l1nb1 = (const float*)d_in[8];
    const float* l1nw2 = (const float*)d_in[9];   // [128,128]
    const float* l1nb2 = (const float*)d_in[10];
    const float* l2mw1 = (const float*)d_in[11];  // [129,128]
    const float* l2mb1 = (const float*)d_in[12];
    const float* l2mw2 = (const float*)d_in[13];  // [128,128]
    const float* l2mb2 = (const float*)d_in[14];
    const float* l2nw1 = (const float*)d_in[15];  // [256,128]
    const float* l2nb1 = (const float*)d_in[16];
    const float* l2nw2 = (const float*)d_in[17];  // [128,2]
    const float* l2nb2 = (const float*)d_in[18];
    float* out = (float*)d_out;

    __nv_bfloat16 *xh, *xl, *Wt1h, *Wt1l, *Wf1h, *Wf1l, *Wf2h, *Wf2l, *Whth, *Whtl;
    __nv_bfloat16 *hbh, *hbl, *hidh, *hidl;
    float *XW, *HW2, *hidden, *proj, *bf1, *bf2, *bh;
    int *cnt, *pos, *counter;
    cudaGetSymbolAddress((void**)&xh,   g_xh);
    cudaGetSymbolAddress((void**)&xl,   g_xl);
    cudaGetSymbolAddress((void**)&Wt1h, g_Wt1h);
    cudaGetSymbolAddress((void**)&Wt1l, g_Wt1l);
    cudaGetSymbolAddress((void**)&Wf1h, g_Wf1h);
    cudaGetSymbolAddress((void**)&Wf1l, g_Wf1l);
    cudaGetSymbolAddress((void**)&Wf2h, g_Wf2h);
    cudaGetSymbolAddress((void**)&Wf2l, g_Wf2l);
    cudaGetSymbolAddress((void**)&Whth, g_Whth);
    cudaGetSymbolAddress((void**)&Whtl, g_Whtl);
    cudaGetSymbolAddress((void**)&hbh,  g_hbh);
    cudaGetSymbolAddress((void**)&hbl,  g_hbl);
    cudaGetSymbolAddress((void**)&hidh, g_hidh);
    cudaGetSymbolAddress((void**)&hidl, g_hidl);
    cudaGetSymbolAddress((void**)&XW,   g_XW);
    cudaGetSymbolAddress((void**)&HW2,  g_HW2);
    cudaGetSymbolAddress((void**)&hidden, g_hidden);
    cudaGetSymbolAddress((void**)&proj, g_proj);
    cudaGetSymbolAddress((void**)&bf1,  g_bf1);
    cudaGetSymbolAddress((void**)&bf2,  g_bf2);
    cudaGetSymbolAddress((void**)&bh,   g_bh);
    cudaGetSymbolAddress((void**)&cnt,  g_cnt);
    cudaGetSymbolAddress((void**)&pos,  g_pos);
    cudaGetSymbolAddress((void**)&counter, g_counter);

    cudaFuncSetAttribute(tgemm, cudaFuncAttributeMaxDynamicSharedMemorySize, GSMEM);

    // ---- CSR over src = idxs.flatten() (offsets unordered but disjoint) ----
    cudaMemsetAsync(cnt, 0, NN * sizeof(int));
    cudaMemsetAsync(pos, 0, NN * sizeof(int));
    cudaMemsetAsync(counter, 0, sizeof(int));
    count_kernel<<<(EE + 255) / 256, 256>>>(idxs);
    offs_kernel <<<(NN + 255) / 256, 256>>>();
    fill_kernel <<<(EE + 255) / 256, 256>>>(idxs, ea);

    // ---- operand prep ----
    conv_split<<<(NN * (DD / 4) + 255) / 256, 256>>>(x, xh, xl);
    convT<<<dim3((DD + 255) / 256, 128), 256>>>(l1mw1, DD, 128, Wt1h, Wt1l, 0,   KPAD);
    convT<<<dim3((DD + 255) / 256, 128), 256>>>(l1nw1, DD, 128, Wt1h, Wt1l, 128, KPAD);
    // Wf1 = l1_msg_w2 @ l1 node W1b ; bf1 = l1_msg_b2 @ W1b
    fold_k<<<129, dim3(128, 4)>>>(l1mw2, l1mb2, DD, l1nw1 + (size_t)DD * HH, HH,
                                  Wf1h, Wf1l, 0, HH, bf1);
    // Wf2 = l2_msg_w2 @ l2 node W1b ; bf2 = l2_msg_b2 @ W1b
    fold_k<<<129, dim3(128, 4)>>>(l2mw2, l2mb2, HH, l2nw1 + (size_t)HH * HH, HH,
                                  Wf2h, Wf2l, 0, HH, bf2);
    // Wh = l1_node_w2 @ [l2 W1x_msg | l2 W1a_node] ; bh likewise
    fold_k<<<129, dim3(128, 4)>>>(l1nw2, l1nb2, HH, l2mw1, HH, Whth, Whtl, 0,   HH, bh);
    fold_k<<<129, dim3(128, 4)>>>(l1nw2, l1nb2, HH, l2nw1, HH, Whth, Whtl, 128, HH, bh + 128);

    // ---- layer 1 ----
    // XW = x @ [W1x_msg | W1a_node]   [N,256]
    tgemm<<<dim3(2, 157), 256, GSMEM>>>(
        xh, xl, KPAD, Wt1h, Wt1l, KPAD, KPAD, NN,
        XW, 256, nullptr, nullptr, nullptr, nullptr, 0, 0,
        nullptr, nullptr);
    // hbar = mean_e relu(XW[:, :128][src] + a*we1 + b1)   (bf16 pair)
    edge_agg<<<NN, HH>>>(XW, 256, l1mw1 + (size_t)DD * HH, l1mb1, hbh, hbl);
    // hidden1 = relu(hbar@Wf1 + XW[:,128:] + l1nb1 + [cnt>0]*bf1) -> bf16 pair
    tgemm<<<dim3(1, 157), 256, GSMEM>>>(
        hbh, hbl, HH, Wf1h, Wf1l, HH, HH, NN,
        nullptr, 0, l1nb1, bf1, cnt, XW + 128, 256, 1,
        hidh, hidl);

    // ---- layer 2 (intermediate h folded away) ----
    // HW2 = hidden1 @ Wh + bh          [N,256]
    tgemm<<<dim3(2, 157), 256, GSMEM>>>(
        hidh, hidl, HH, Whth, Whtl, HH, HH, NN,
        HW2, 256, bh, nullptr, nullptr, nullptr, 0, 0,
        nullptr, nullptr);
    // hbar2 = mean_e relu(HW2[:, :128][src] + a*we2 + b1)
    edge_agg<<<NN, HH>>>(HW2, 256, l2mw1 + (size_t)HH * HH, l2mb1, hbh, hbl);
    // hidden2 = relu(hbar2@Wf2 + HW2[:,128:] + l2nb1 + [cnt>0]*bf2)  (f32)
    tgemm<<<dim3(1, 157), 256, GSMEM>>>(
        hbh, hbl, HH, Wf2h, Wf2l, HH, HH, NN,
        hidden, HH, l2nb1, bf2, cnt, HW2 + 128, 256, 1,
        nullptr, nullptr);

    // ---- output ----
    proj_kernel<<<(NN * 32 + 255) / 256, 256>>>(hidden, l2nw2, l2nb2, proj);
    dist_kernel<<<(EE + 255) / 256, 256>>>(proj, idxs, out);
}

// round 7
// speedup vs baseline: 3.9524x; 1.0700x over previous
#include <cuda_runtime.h>
#include <cuda_bf16.h>
#include <cstdint>

// Problem constants (fixed by the reference)
#define NN 10000          // nodes
#define DD 784            // input feat dim
#define KPAD 800          // DD padded to multiple of 32 (pad cols stay zero)
#define KK 16             // neighbors+1
#define EE (NN * (KK-1))  // edges = 150000
#define HH 128            // hidden width

// ============================ scratch globals ===============================
__device__ __align__(256) __nv_bfloat16 g_xh   [NN * KPAD];
__device__ __align__(256) __nv_bfloat16 g_xl   [NN * KPAD];
__device__ __align__(256) __nv_bfloat16 g_Wt1h [256 * KPAD]; // [l1 msgW1x^T ; l1 nodeW1a^T]
__device__ __align__(256) __nv_bfloat16 g_Wt1l [256 * KPAD];
__device__ __align__(256) __nv_bfloat16 g_Wf1h [HH * HH];    // (l1 msgW2 @ l1 nodeW1b)^T
__device__ __align__(256) __nv_bfloat16 g_Wf1l [HH * HH];
__device__ __align__(256) __nv_bfloat16 g_Wf2h [HH * HH];
__device__ __align__(256) __nv_bfloat16 g_Wf2l [HH * HH];
__device__ __align__(256) __nv_bfloat16 g_Whth [256 * HH];   // (l1 nodeW2 @ [l2 W1x | l2 W1a])^T
__device__ __align__(256) __nv_bfloat16 g_Whtl [256 * HH];
__device__ __align__(256) float g_bf1[HH];
__device__ __align__(256) float g_bf2[HH];
__device__ __align__(256) float g_bh [256];
__device__ __align__(256) float g_XW  [NN * 256];
__device__ __align__(256) float g_HW2 [NN * 256];
__device__ __align__(256) __nv_bfloat16 g_hbh [NN * HH];     // hbar hi/lo
__device__ __align__(256) __nv_bfloat16 g_hbl [NN * HH];
__device__ __align__(256) __nv_bfloat16 g_hidh[NN * HH];     // hidden hi/lo
__device__ __align__(256) __nv_bfloat16 g_hidl[NN * HH];
__device__ __align__(256) float g_proj[NN * 2];
__device__ int   g_csr [2 * NN + 1];   // [cnt | pos | counter] -> ONE memset
__device__ int   g_offs[NN];
__device__ __align__(256) float g_bucket[EE];

// ============================ prep megakernel ===============================
// One launch covering the independent prep work:
//   [0, PB_COUNT)  : edge count histogram
//   [.., +PB_CONV) : x f32 -> bf16 hi/lo split
//   [.., +PB_CONVT): transpose+split of l1 msg/node W1 (784x128 -> rows of Wt1)
//   [.., +PB_FOLD) : 4 weight folds (bf16 split + folded bias)
struct FoldArgs {
    const float* A[4];
    const float* avec[4];
    const float* B[4];
    __nv_bfloat16* oh[4];
    __nv_bfloat16* ol[4];
    float* bf[4];
    int Kd[4];
    int row_off[4];
};

#define PB_COUNT 586
#define PB_CONV  7657
#define PB_CONVT 1024     // 2 weights x (4 k-blocks x 128 n)
#define PB_FOLD  516      // 4 folds x 129 rows
#define PB_TOTAL (PB_COUNT + PB_CONV + PB_CONVT + PB_FOLD)

__global__ void __launch_bounds__(256)
prep_mega(const int* __restrict__ idxs, const float* __restrict__ x,
          const float* __restrict__ Wc0, const float* __restrict__ Wc1,
          __nv_bfloat16* __restrict__ xh, __nv_bfloat16* __restrict__ xl,
          __nv_bfloat16* __restrict__ Wt1h, __nv_bfloat16* __restrict__ Wt1l,
          FoldArgs fa) {
    __shared__ float red[256];
    int b = blockIdx.x, tid = threadIdx.x;

    if (b < PB_COUNT) {                       // ---- edge count ----
        int e = b * 256 + tid;
        if (e < EE) atomicAdd(&g_csr[idxs[e]], 1);
        return;
    }
    b -= PB_COUNT;
    if (b < PB_CONV) {                        // ---- x split ----
        int i = b * 256 + tid;
        if (i >= NN * (DD / 4)) return;
        int row = i / (DD / 4), c = i % (DD / 4);
        float4 v = ((const float4*)(x + (size_t)row * DD))[c];
        __nv_bfloat16 h0 = __float2bfloat16(v.x), h1 = __float2bfloat16(v.y);
        __nv_bfloat16 h2 = __float2bfloat16(v.z), h3 = __float2bfloat16(v.w);
        __nv_bfloat16 l0 = __float2bfloat16(v.x - __bfloat162float(h0));
        __nv_bfloat16 l1 = __float2bfloat16(v.y - __bfloat162float(h1));
        __nv_bfloat16 l2 = __float2bfloat16(v.z - __bfloat162float(h2));
        __nv_bfloat16 l3 = __float2bfloat16(v.w - __bfloat162float(h3));
        size_t o = (size_t)row * KPAD + c * 4;
        *(__nv_bfloat162*)(xh + o)     = __nv_bfloat162(h0, h1);
        *(__nv_bfloat162*)(xh + o + 2) = __nv_bfloat162(h2, h3);
        *(__nv_bfloat162*)(xl + o)     = __nv_bfloat162(l0, l1);
        *(__nv_bfloat162*)(xl + o + 2) = __nv_bfloat162(l2, l3);
        return;
    }
    b -= PB_CONV;
    if (b < PB_CONVT) {                       // ---- W1 transpose+split ----
        int z = b >> 9;                       // which weight (0/1)
        int rem = b & 511;
        int kb = rem & 3, n = rem >> 2;
        int k = kb * 256 + tid;
        if (k >= DD) return;
        const float* W = z ? Wc1 : Wc0;
        float v = W[(size_t)k * 128 + n];
        __nv_bfloat16 h = __float2bfloat16(v);
        size_t o = (size_t)(z * 128 + n) * KPAD + k;
        Wt1h[o] = h;
        Wt1l[o] = __float2bfloat16(v - __bfloat162float(h));
        return;
    }
    b -= PB_CONVT;
    {                                         // ---- weight folds ----
        int f = b / 129, i = b % 129;
        int j = tid & 127, kq = tid >> 7;     // 2-way K split
        int Kd = fa.Kd[f];
        const float* arow = (i < 128) ? (fa.A[f] + (size_t)i * Kd) : fa.avec[f];
        const float* B = fa.B[f];
        int chunk = (Kd + 1) >> 1;
        int k0 = kq * chunk, k1 = min(Kd, k0 + chunk);
        float s = 0.f;
        #pragma unroll 4
        for (int k = k0; k < k1; k++)
            s = fmaf(__ldg(&arow[k]), B[(size_t)k * HH + j], s);
        red[tid] = s;
        __syncthreads();
        if (kq == 0) {
            s = red[j] + red[128 + j];
            if (i < 128) {
                __nv_bfloat16 h = __float2bfloat16(s);
                size_t o = (size_t)(fa.row_off[f] + j) * HH + i;
                fa.oh[f][o] = h;
                fa.ol[f][o] = __float2bfloat16(s - __bfloat162float(h));
            } else {
                fa.bf[f][j] = s;
            }
        }
        return;
    }
}

// offsets need only be disjoint ranges, not ordered -> block scan + atomic base
__global__ void offs_kernel() {
    __shared__ int sd[256];
    __shared__ int base_s;
    int t = threadIdx.x;
    int i = blockIdx.x * 256 + t;
    int v = (i < NN) ? g_csr[i] : 0;
    sd[t] = v;
    __syncthreads();
    #pragma unroll
    for (int o = 1; o < 256; o <<= 1) {
        int x = (t >= o) ? sd[t - o] : 0;
        __syncthreads();
        sd[t] += x;
        __syncthreads();
    }
    if (t == 255) base_s = atomicAdd(&g_csr[2 * NN], sd[255]);
    __syncthreads();
    if (i < NN) g_offs[i] = base_s + sd[t] - v;
}

__global__ void fill_kernel(const int* __restrict__ idxs,
                            const float* __restrict__ ea) {
    int e = blockIdx.x * blockDim.x + threadIdx.x;
    if (e < EE) {
        int s = idxs[e];
        int p = atomicAdd(&g_csr[NN + s], 1);
        g_bucket[g_offs[s] + p] = ea[e];
    }
}

// flat per-(node,col) edge aggregation; 32-lane warp shares one node so the
// bucket loads are warp-uniform broadcasts.
__global__ void edge_agg(const float* __restrict__ xw, int ld,
                         const float* __restrict__ we,
                         const float* __restrict__ b,
                         __nv_bfloat16* __restrict__ oh,
                         __nv_bfloat16* __restrict__ ol) {
    int idx = blockIdx.x * blockDim.x + threadIdx.x;
    if (idx >= NN * HH) return;
    int m = idx >> 7;
    int j = idx & 127;
    int deg = g_csr[m];
    int start = g_offs[m];
    float xj = xw[(size_t)m * ld + j] + __ldg(&b[j]);
    float wj = __ldg(&we[j]);
    float s = 0.f;
    for (int t = 0; t < deg; t++)
        s += fmaxf(fmaf(g_bucket[start + t], wj, xj), 0.f);
    float v = deg ? s / (float)deg : 0.f;
    __nv_bfloat16 h = __float2bfloat16(v);
    oh[(size_t)m * HH + j] = h;
    ol[(size_t)m * HH + j] = __float2bfloat16(v - __bfloat162float(h));
}

// ============================ mma.sync GEMM ================================
// C[M,Ntot] = (Ah+Al)[M,K] @ (Bh+Bl)^T (B stored [Ntot][K]); 3-product split.
// Block tile 64x128, BK=32, 8 warps (2 M x 4 N), 3-stage cp.async pipeline.
// Optional fused row-projection: projOut[gm] = row(gm) @ projW + projB.
#define TPITCH 40                      // bf16 pitch (80 B) per smem tile row
#define TILE_A (64 * TPITCH * 2)       // 5120 B
#define TILE_B (128 * TPITCH * 2)      // 10240 B
#define STAGE_B (2 * TILE_A + 2 * TILE_B)   // 30720 B: AH AL BH BL
#define GSMEM (3 * STAGE_B)            // 92160 B

__device__ __forceinline__ uint32_t smem_u32(const void* p) {
    uint32_t a;
    asm("{ .reg .u64 t; cvta.to.shared.u64 t, %1; cvt.u32.u64 %0, t; }"
        : "=r"(a) : "l"(p));
    return a;
}
__device__ __forceinline__ void cp16(uint32_t dst, const void* src, int sz) {
    asm volatile("cp.async.cg.shared.global [%0], [%1], 16, %2;"
        :: "r"(dst), "l"(src), "r"(sz) : "memory");
}
__device__ __forceinline__ void ldsm_x4(uint32_t* r, uint32_t a) {
    asm volatile("ldmatrix.sync.aligned.m8n8.x4.shared.b16 {%0,%1,%2,%3}, [%4];"
        : "=r"(r[0]), "=r"(r[1]), "=r"(r[2]), "=r"(r[3]) : "r"(a));
}
__device__ __forceinline__ void ldsm_x2(uint32_t* r, uint32_t a) {
    asm volatile("ldmatrix.sync.aligned.m8n8.x2.shared.b16 {%0,%1}, [%2];"
        : "=r"(r[0]), "=r"(r[1]) : "r"(a));
}
__device__ __forceinline__ void mma_bf16(float* c, const uint32_t* a, const uint32_t* b) {
    asm volatile("mma.sync.aligned.m16n8k16.row.col.f32.bf16.bf16.f32 "
        "{%0,%1,%2,%3}, {%4,%5,%6,%7}, {%8,%9}, {%0,%1,%2,%3};"
        : "+f"(c[0]), "+f"(c[1]), "+f"(c[2]), "+f"(c[3])
        : "r"(a[0]), "r"(a[1]), "r"(a[2]), "r"(a[3]), "r"(b[0]), "r"(b[1]));
}

__global__ void __launch_bounds__(256)
tgemm(const __nv_bfloat16* __restrict__ Ah, const __nv_bfloat16* __restrict__ Al,
      int lda,
      const __nv_bfloat16* __restrict__ Bh, const __nv_bfloat16* __restrict__ Bl,
      int ldb, int K, int M,
      float* __restrict__ C, int ldc,
      const float* __restrict__ bias,
      const float* __restrict__ cbias, const int* __restrict__ cnt,
      const float* __restrict__ addend, int addld, int relu,
      __nv_bfloat16* __restrict__ outHi, __nv_bfloat16* __restrict__ outLo,
      const float* __restrict__ projW, const float* __restrict__ projB,
      float* __restrict__ projOut) {
    extern __shared__ char smem[];
    uint32_t sb = smem_u32(smem);
    int tid = threadIdx.x;
    int wid = tid >> 5, lane = tid & 31;
    int bm = blockIdx.y * 64;
    int bn = blockIdx.x * 128;
    int wr = wid & 1;        // M warp (0..1), 32 rows each
    int wc = wid >> 1;       // N warp (0..3), 32 cols each

    const __nv_bfloat16* srcs[4] = {Ah, Al, Bh, Bl};
    const int toff[4] = {0, TILE_A, 2 * TILE_A, 2 * TILE_A + TILE_B};

    auto issue = [&](int kc, int stg) {
        int k0 = kc * 32;
        #pragma unroll
        for (int u = 0; u < 6; u++) {
            int idx = tid + u * 256;          // 0..1535
            int tile, row;
            if (idx < 512) { tile = idx >> 8; row = (idx & 255) >> 2; }
            else { tile = 2 + ((idx - 512) >> 9); row = ((idx - 512) & 511) >> 2; }
            int c = idx & 3;
            int gr, maxr;
            if (tile < 2) { gr = bm + row; maxr = M; }
            else          { gr = bn + row; maxr = 1 << 30; }
            const __nv_bfloat16* s = srcs[tile] +
                (size_t)gr * ((tile < 2) ? lda : ldb) + k0 + c * 8;
            uint32_t d = sb + stg * STAGE_B + toff[tile] + row * (TPITCH * 2) + c * 16;
            cp16(d, s, (gr < maxr) ? 16 : 0);
        }
        asm volatile("cp.async.commit_group;" ::: "memory");
    };

    float acc[2][4][4] = {};
    int nT = K / 32;

    issue(0, 0);
    if (nT > 1) issue(1, 1);
    for (int t = 0; t < nT; t++) {
        int stg = t % 3;
        if (t + 2 < nT) {
            issue(t + 2, (t + 2) % 3);
            asm volatile("cp.async.wait_group 2;" ::: "memory");
        } else if (t + 1 < nT) {
            asm volatile("cp.async.wait_group 1;" ::: "memory");
        } else {
            asm volatile("cp.async.wait_group 0;" ::: "memory");
        }
        __syncthreads();

        uint32_t baseAH = sb + stg * STAGE_B + toff[0];
        uint32_t baseAL = sb + stg * STAGE_B + toff[1];
        uint32_t baseBH = sb + stg * STAGE_B + toff[2];
        uint32_t baseBL = sb + stg * STAGE_B + toff[3];

        #pragma unroll
        for (int ks = 0; ks < 2; ks++) {
            uint32_t aH[2][4], aL[2][4], bH[4][2], bL[4][2];
            int acol = (ks * 16 + (lane >> 4) * 8) * 2;
            int bcol = (ks * 16 + ((lane >> 3) & 1) * 8) * 2;
            #pragma unroll
            for (int mi = 0; mi < 2; mi++) {
                int arow = wr * 32 + mi * 16 + (lane & 15);
                ldsm_x4(aH[mi], baseAH + arow * (TPITCH * 2) + acol);
                ldsm_x4(aL[mi], baseAL + arow * (TPITCH * 2) + acol);
            }
            #pragma unroll
            for (int ni = 0; ni < 4; ni++) {
                int brow = wc * 32 + ni * 8 + (lane & 7);
                ldsm_x2(bH[ni], baseBH + brow * (TPITCH * 2) + bcol);
                ldsm_x2(bL[ni], baseBL + brow * (TPITCH * 2) + bcol);
            }
            #pragma unroll
            for (int mi = 0; mi < 2; mi++)
                #pragma unroll
                for (int ni = 0; ni < 4; ni++) {
                    mma_bf16(acc[mi][ni], aH[mi], bH[ni]);
                    mma_bf16(acc[mi][ni], aH[mi], bL[ni]);
                    mma_bf16(acc[mi][ni], aL[mi], bH[ni]);
                }
        }
        __syncthreads();
    }

    // ---- epilogue ----
    float* pbuf = (float*)smem;               // 64 rows x 2 proj accumulators
    if (projOut) {
        for (int i = tid; i < 128; i += 256) pbuf[i] = 0.f;
        __syncthreads();
    }
    float pacc[2][2][2] = {};
    #pragma unroll
    for (int mi = 0; mi < 2; mi++) {
        #pragma unroll
        for (int half = 0; half < 2; half++) {
            int gm = bm + wr * 32 + mi * 16 + (lane >> 2) + half * 8;
            if (gm >= M) continue;
            bool cb = (cbias != nullptr) && (cnt[gm] > 0);
            #pragma unroll
            for (int ni = 0; ni < 4; ni++) {
                #pragma unroll
                for (int e = 0; e < 2; e++) {
                    int gn = bn + wc * 32 + ni * 8 + (lane & 3) * 2 + e;
                    float v = acc[mi][ni][half * 2 + e];
                    if (bias)   v += __ldg(&bias[gn]);
                    if (cb)     v += __ldg(&cbias[gn]);
                    if (addend) v += addend[(size_t)gm * addld + gn];
                    if (relu)   v = fmaxf(v, 0.f);
                    if (C) C[(size_t)gm * ldc + gn] = v;
                    if (outHi) {
                        __nv_bfloat16 h = __float2bfloat16(v);
                        outHi[(size_t)gm * 128 + gn] = h;
                        outLo[(size_t)gm * 128 + gn] =
                            __float2bfloat16(v - __bfloat162float(h));
                    }
                    if (projOut) {
                        pacc[mi][half][0] = fmaf(v, __ldg(&projW[gn * 2 + 0]),
                                                 pacc[mi][half][0]);
                        pacc[mi][half][1] = fmaf(v, __ldg(&projW[gn * 2 + 1]),
                                                 pacc[mi][half][1]);
                    }
                }
            }
        }
    }
    if (projOut) {
        #pragma unroll
        for (int mi = 0; mi < 2; mi++)
            #pragma unroll
            for (int half = 0; half < 2; half++) {
                int rl = wr * 32 + mi * 16 + (lane >> 2) + half * 8;
                if (bm + rl < M) {
                    atomicAdd(&pbuf[rl * 2 + 0], pacc[mi][half][0]);
                    atomicAdd(&pbuf[rl * 2 + 1], pacc[mi][half][1]);
                }
            }
        __syncthreads();
        if (tid < 128) {
            int r = tid >> 1, c = tid & 1;
            if (bm + r < M)
                projOut[(bm + r) * 2 + c] = pbuf[tid] + __ldg(&projB[c]);
        }
    }
}

// ---------------- pairwise squared distances -------------------------------
__global__ void dist_kernel(const float* __restrict__ proj,
                            const int* __restrict__ idxs,
                            float* __restrict__ out) {
    int i = blockIdx.x * blockDim.x + threadIdx.x;
    if (i >= EE) return;
    int n  = i / (KK - 1);
    int nb = idxs[i];
    float dx = proj[n * 2 + 0] - proj[nb * 2 + 0];
    float dy = proj[n * 2 + 1] - proj[nb * 2 + 1];
    out[i] = dx * dx + dy * dy;
}

// ============================ launch ========================================
extern "C" void kernel_launch(void* const* d_in, const int* in_sizes, int n_in,
                              void* d_out, int out_size) {
    const float* x     = (const float*)d_in[0];
    const float* ea    = (const float*)d_in[1];
    const int*   idxs  = (const int*)  d_in[2];
    const float* l1mw1 = (const float*)d_in[3];   // [785,128]
    const float* l1mb1 = (const float*)d_in[4];
    const float* l1mw2 = (const float*)d_in[5];   // [128,784]
    const float* l1mb2 = (const float*)d_in[6];
    const float* l1nw1 = (const float*)d_in[7];   // [1568,128]
    const float* l1nb1 = (const float*)d_in[8];
    const float* l1nw2 = (const float*)d_in[9];   // [128,128]
    const float* l1nb2 = (const float*)d_in[10];
    const float* l2mw1 = (const float*)d_in[11];  // [129,128]
    const float* l2mb1 = (const float*)d_in[12];
    const float* l2mw2 = (const float*)d_in[13];  // [128,128]
    const float* l2mb2 = (const float*)d_in[14];
    const float* l2nw1 = (const float*)d_in[15];  // [256,128]
    const float* l2nb1 = (const float*)d_in[16];
    const float* l2nw2 = (const float*)d_in[17];  // [128,2]
    const float* l2nb2 = (const float*)d_in[18];
    float* out = (float*)d_out;

    __nv_bfloat16 *xh, *xl, *Wt1h, *Wt1l, *Wf1h, *Wf1l, *Wf2h, *Wf2l, *Whth, *Whtl;
    __nv_bfloat16 *hbh, *hbl, *hidh, *hidl;
    float *XW, *HW2, *proj, *bf1, *bf2, *bh;
    int *csr;
    cudaGetSymbolAddress((void**)&xh,   g_xh);
    cudaGetSymbolAddress((void**)&xl,   g_xl);
    cudaGetSymbolAddress((void**)&Wt1h, g_Wt1h);
    cudaGetSymbolAddress((void**)&Wt1l, g_Wt1l);
    cudaGetSymbolAddress((void**)&Wf1h, g_Wf1h);
    cudaGetSymbolAddress((void**)&Wf1l, g_Wf1l);
    cudaGetSymbolAddress((void**)&Wf2h, g_Wf2h);
    cudaGetSymbolAddress((void**)&Wf2l, g_Wf2l);
    cudaGetSymbolAddress((void**)&Whth, g_Whth);
    cudaGetSymbolAddress((void**)&Whtl, g_Whtl);
    cudaGetSymbolAddress((void**)&hbh,  g_hbh);
    cudaGetSymbolAddress((void**)&hbl,  g_hbl);
    cudaGetSymbolAddress((void**)&hidh, g_hidh);
    cudaGetSymbolAddress((void**)&hidl, g_hidl);
    cudaGetSymbolAddress((void**)&XW,   g_XW);
    cudaGetSymbolAddress((void**)&HW2,  g_HW2);
    cudaGetSymbolAddress((void**)&proj, g_proj);
    cudaGetSymbolAddress((void**)&bf1,  g_bf1);
    cudaGetSymbolAddress((void**)&bf2,  g_bf2);
    cudaGetSymbolAddress((void**)&bh,   g_bh);
    cudaGetSymbolAddress((void**)&csr,  g_csr);
    int* cnt = csr;   // first NN entries

    cudaFuncSetAttribute(tgemm, cudaFuncAttributeMaxDynamicSharedMemorySize, GSMEM);

    // ---- single memset for cnt/pos/counter ----
    cudaMemsetAsync(csr, 0, (2 * NN + 1) * sizeof(int));

    // ---- fold argument pack ----
    FoldArgs fa;
    fa.A[0] = l1mw2;  fa.avec[0] = l1mb2;  fa.B[0] = l1nw1 + (size_t)DD * HH;
    fa.oh[0] = Wf1h;  fa.ol[0] = Wf1l;     fa.bf[0] = bf1;
    fa.Kd[0] = DD;    fa.row_off[0] = 0;
    fa.A[1] = l2mw2;  fa.avec[1] = l2mb2;  fa.B[1] = l2nw1 + (size_t)HH * HH;
    fa.oh[1] = Wf2h;  fa.ol[1] = Wf2l;     fa.bf[1] = bf2;
    fa.Kd[1] = HH;    fa.row_off[1] = 0;
    fa.A[2] = l1nw2;  fa.avec[2] = l1nb2;  fa.B[2] = l2mw1;
    fa.oh[2] = Whth;  fa.ol[2] = Whtl;     fa.bf[2] = bh;
    fa.Kd[2] = HH;    fa.row_off[2] = 0;
    fa.A[3] = l1nw2;  fa.avec[3] = l1nb2;  fa.B[3] = l2nw1;
    fa.oh[3] = Whth;  fa.ol[3] = Whtl;     fa.bf[3] = bh + 128;
    fa.Kd[3] = HH;    fa.row_off[3] = 128;

    // ---- prep: count + conv + convT + folds in ONE launch ----
    prep_mega<<<PB_TOTAL, 256>>>(idxs, x, l1mw1, l1nw1, xh, xl, Wt1h, Wt1l, fa);
    offs_kernel<<<(NN + 255) / 256, 256>>>();
    fill_kernel<<<(EE + 255) / 256, 256>>>(idxs, ea);

    // ---- layer 1 ----
    // XW = x @ [W1x_msg | W1a_node]   [N,256]
    tgemm<<<dim3(2, 157), 256, GSMEM>>>(
        xh, xl, KPAD, Wt1h, Wt1l, KPAD, KPAD, NN,
        XW, 256, nullptr, nullptr, nullptr, nullptr, 0, 0,
        nullptr, nullptr, nullptr, nullptr, nullptr);
    // hbar = mean_e relu(XW[:, :128][src] + a*we1 + b1)   (bf16 pair)
    edge_agg<<<(NN * HH + 255) / 256, 256>>>(XW, 256, l1mw1 + (size_t)DD * HH,
                                             l1mb1, hbh, hbl);
    // hidden1 = relu(hbar@Wf1 + XW[:,128:] + l1nb1 + [cnt>0]*bf1) -> bf16 pair
    tgemm<<<dim3(1, 157), 256, GSMEM>>>(
        hbh, hbl, HH, Wf1h, Wf1l, HH, HH, NN,
        nullptr, 0, l1nb1, bf1, cnt, XW + 128, 256, 1,
        hidh, hidl, nullptr, nullptr, nullptr);

    // ---- layer 2 (intermediate h folded away) ----
    // HW2 = hidden1 @ Wh + bh          [N,256]
    tgemm<<<dim3(2, 157), 256, GSMEM>>>(
        hidh, hidl, HH, Whth, Whtl, HH, HH, NN,
        HW2, 256, bh, nullptr, nullptr, nullptr, 0, 0,
        nullptr, nullptr, nullptr, nullptr, nullptr);
    // hbar2 = mean_e relu(HW2[:, :128][src] + a*we2 + b1)
    edge_agg<<<(NN * HH + 255) / 256, 256>>>(HW2, 256, l2mw1 + (size_t)HH * HH,
                                             l2mb1, hbh, hbl);
    // hidden2 = relu(hbar2@Wf2 + HW2[:,128:] + l2nb1 + [cnt>0]*bf2) -> fused proj
    tgemm<<<dim3(1, 157), 256, GSMEM>>>(
        hbh, hbl, HH, Wf2h, Wf2l, HH, HH, NN,
        nullptr, 0, l2nb1, bf2, cnt, HW2 + 128, 256, 1,
        nullptr, nullptr, l2nw2, l2nb2, proj);

    // ---- output ----
    dist_kernel<<<(EE + 255) / 256, 256>>>(proj, idxs, out);
}

// round 8
// speedup vs baseline: 4.0654x; 1.0286x over previous
#include <cuda_runtime.h>
#include <cuda_bf16.h>
#include <cstdint>

// Problem constants (fixed by the reference)
#define NN 10000          // nodes
#define DD 784            // input feat dim
#define KPAD 800          // DD padded to multiple of 32 (pad cols stay zero)
#define KK 16             // neighbors+1
#define EE (NN * (KK-1))  // edges = 150000
#define HH 128            // hidden width

// ============================ scratch globals ===============================
__device__ __align__(256) __nv_bfloat16 g_xh   [NN * KPAD];
__device__ __align__(256) __nv_bfloat16 g_xl   [NN * KPAD];
__device__ __align__(256) __nv_bfloat16 g_Wt1h [256 * KPAD]; // [l1 msgW1x^T ; l1 nodeW1a^T]
__device__ __align__(256) __nv_bfloat16 g_Wt1l [256 * KPAD];
__device__ __align__(256) __nv_bfloat16 g_Wf1h [HH * HH];    // (l1 msgW2 @ l1 nodeW1b)^T
__device__ __align__(256) __nv_bfloat16 g_Wf1l [HH * HH];
__device__ __align__(256) __nv_bfloat16 g_Wf2h [HH * HH];
__device__ __align__(256) __nv_bfloat16 g_Wf2l [HH * HH];
__device__ __align__(256) __nv_bfloat16 g_Whth [256 * HH];   // (l1 nodeW2 @ [l2 W1x | l2 W1a])^T
__device__ __align__(256) __nv_bfloat16 g_Whtl [256 * HH];
__device__ __align__(256) float g_bf1[HH];
__device__ __align__(256) float g_bf2[HH];
__device__ __align__(256) float g_bh [256];
__device__ __align__(256) float g_XW  [NN * 256];
__device__ __align__(256) float g_HW2 [NN * 256];
__device__ __align__(256) __nv_bfloat16 g_hbh [NN * HH];     // hbar hi/lo
__device__ __align__(256) __nv_bfloat16 g_hbl [NN * HH];
__device__ __align__(256) __nv_bfloat16 g_hidh[NN * HH];     // hidden hi/lo
__device__ __align__(256) __nv_bfloat16 g_hidl[NN * HH];
__device__ __align__(256) float g_proj[NN * 2];
__device__ int   g_csr [2 * NN + 1];   // [cnt | pos | counter] -> ONE memset
__device__ int   g_offs[NN];
__device__ __align__(256) float g_bucket[EE];

// ============================ prep megakernel ===============================
struct FoldArgs {
    const float* A[4];
    const float* avec[4];
    const float* B[4];
    __nv_bfloat16* oh[4];
    __nv_bfloat16* ol[4];
    float* bf[4];
    int Kd[4];
    int row_off[4];
};

#define PB_COUNT 586
#define PB_CONV  7657
#define PB_CONVT 1024     // 2 weights x (4 k-blocks x 128 n)
#define PB_FOLD  516      // 4 folds x 129 rows
#define PB_TOTAL (PB_COUNT + PB_CONV + PB_CONVT + PB_FOLD)

__global__ void __launch_bounds__(256)
prep_mega(const int* __restrict__ idxs, const float* __restrict__ x,
          const float* __restrict__ Wc0, const float* __restrict__ Wc1,
          __nv_bfloat16* __restrict__ xh, __nv_bfloat16* __restrict__ xl,
          __nv_bfloat16* __restrict__ Wt1h, __nv_bfloat16* __restrict__ Wt1l,
          FoldArgs fa) {
    __shared__ float red[256];
    int b = blockIdx.x, tid = threadIdx.x;

    if (b < PB_COUNT) {                       // ---- edge count ----
        int e = b * 256 + tid;
        if (e < EE) atomicAdd(&g_csr[idxs[e]], 1);
        return;
    }
    b -= PB_COUNT;
    if (b < PB_CONV) {                        // ---- x split ----
        int i = b * 256 + tid;
        if (i >= NN * (DD / 4)) return;
        int row = i / (DD / 4), c = i % (DD / 4);
        float4 v = ((const float4*)(x + (size_t)row * DD))[c];
        __nv_bfloat16 h0 = __float2bfloat16(v.x), h1 = __float2bfloat16(v.y);
        __nv_bfloat16 h2 = __float2bfloat16(v.z), h3 = __float2bfloat16(v.w);
        __nv_bfloat16 l0 = __float2bfloat16(v.x - __bfloat162float(h0));
        __nv_bfloat16 l1 = __float2bfloat16(v.y - __bfloat162float(h1));
        __nv_bfloat16 l2 = __float2bfloat16(v.z - __bfloat162float(h2));
        __nv_bfloat16 l3 = __float2bfloat16(v.w - __bfloat162float(h3));
        size_t o = (size_t)row * KPAD + c * 4;
        *(__nv_bfloat162*)(xh + o)     = __nv_bfloat162(h0, h1);
        *(__nv_bfloat162*)(xh + o + 2) = __nv_bfloat162(h2, h3);
        *(__nv_bfloat162*)(xl + o)     = __nv_bfloat162(l0, l1);
        *(__nv_bfloat162*)(xl + o + 2) = __nv_bfloat162(l2, l3);
        return;
    }
    b -= PB_CONV;
    if (b < PB_CONVT) {                       // ---- W1 transpose+split ----
        int z = b >> 9;                       // which weight (0/1)
        int rem = b & 511;
        int kb = rem & 3, n = rem >> 2;
        int k = kb * 256 + tid;
        if (k >= DD) return;
        const float* W = z ? Wc1 : Wc0;
        float v = W[(size_t)k * 128 + n];
        __nv_bfloat16 h = __float2bfloat16(v);
        size_t o = (size_t)(z * 128 + n) * KPAD + k;
        Wt1h[o] = h;
        Wt1l[o] = __float2bfloat16(v - __bfloat162float(h));
        return;
    }
    b -= PB_CONVT;
    {                                         // ---- weight folds ----
        int f = b / 129, i = b % 129;
        int j = tid & 127, kq = tid >> 7;     // 2-way K split
        int Kd = fa.Kd[f];
        const float* arow = (i < 128) ? (fa.A[f] + (size_t)i * Kd) : fa.avec[f];
        const float* B = fa.B[f];
        int chunk = (Kd + 1) >> 1;
        int k0 = kq * chunk, k1 = min(Kd, k0 + chunk);
        float s = 0.f;
        #pragma unroll 4
        for (int k = k0; k < k1; k++)
            s = fmaf(__ldg(&arow[k]), B[(size_t)k * HH + j], s);
        red[tid] = s;
        __syncthreads();
        if (kq == 0) {
            s = red[j] + red[128 + j];
            if (i < 128) {
                __nv_bfloat16 h = __float2bfloat16(s);
                size_t o = (size_t)(fa.row_off[f] + j) * HH + i;
                fa.oh[f][o] = h;
                fa.ol[f][o] = __float2bfloat16(s - __bfloat162float(h));
            } else {
                fa.bf[f][j] = s;
            }
        }
        return;
    }
}

// offsets need only be disjoint ranges, not ordered -> block scan + atomic base
__global__ void offs_kernel() {
    __shared__ int sd[256];
    __shared__ int base_s;
    int t = threadIdx.x;
    int i = blockIdx.x * 256 + t;
    int v = (i < NN) ? g_csr[i] : 0;
    sd[t] = v;
    __syncthreads();
    #pragma unroll
    for (int o = 1; o < 256; o <<= 1) {
        int x = (t >= o) ? sd[t - o] : 0;
        __syncthreads();
        sd[t] += x;
        __syncthreads();
    }
    if (t == 255) base_s = atomicAdd(&g_csr[2 * NN], sd[255]);
    __syncthreads();
    if (i < NN) g_offs[i] = base_s + sd[t] - v;
}

__global__ void fill_kernel(const int* __restrict__ idxs,
                            const float* __restrict__ ea) {
    int e = blockIdx.x * blockDim.x + threadIdx.x;
    if (e < EE) {
        int s = idxs[e];
        int p = atomicAdd(&g_csr[NN + s], 1);
        g_bucket[g_offs[s] + p] = ea[e];
    }
}

// flat per-(node,col) edge aggregation; 32-lane warp shares one node so the
// bucket loads are warp-uniform broadcasts.
__global__ void edge_agg(const float* __restrict__ xw, int ld,
                         const float* __restrict__ we,
                         const float* __restrict__ b,
                         __nv_bfloat16* __restrict__ oh,
                         __nv_bfloat16* __restrict__ ol) {
    int idx = blockIdx.x * blockDim.x + threadIdx.x;
    if (idx >= NN * HH) return;
    int m = idx >> 7;
    int j = idx & 127;
    int deg = g_csr[m];
    int start = g_offs[m];
    float xj = xw[(size_t)m * ld + j] + __ldg(&b[j]);
    float wj = __ldg(&we[j]);
    float s = 0.f;
    for (int t = 0; t < deg; t++)
        s += fmaxf(fmaf(g_bucket[start + t], wj, xj), 0.f);
    float v = deg ? s / (float)deg : 0.f;
    __nv_bfloat16 h = __float2bfloat16(v);
    oh[(size_t)m * HH + j] = h;
    ol[(size_t)m * HH + j] = __float2bfloat16(v - __bfloat162float(h));
}

// ============================ mma.sync GEMM ================================
// C[M,Ntot] = (Ah+Al)[M,K] @ (Bh+Bl)^T (B stored [Ntot][K]); 3-product split.
// Block tile 64x128, BK=32, 8 warps (2 M x 4 N), 2-stage cp.async pipeline
// (3 CTAs/SM). B fragments loaded with ldmatrix.x4 (two n-tiles per load).
#define TPITCH 40                      // bf16 pitch (80 B) per smem tile row
#define TILE_A (64 * TPITCH * 2)       // 5120 B
#define TILE_B (128 * TPITCH * 2)      // 10240 B
#define STAGE_B (2 * TILE_A + 2 * TILE_B)   // 30720 B: AH AL BH BL
#define GSMEM (2 * STAGE_B)            // 61440 B -> 3 CTAs/SM

__device__ __forceinline__ uint32_t smem_u32(const void* p) {
    uint32_t a;
    asm("{ .reg .u64 t; cvta.to.shared.u64 t, %1; cvt.u32.u64 %0, t; }"
        : "=r"(a) : "l"(p));
    return a;
}
__device__ __forceinline__ void cp16(uint32_t dst, const void* src, int sz) {
    asm volatile("cp.async.cg.shared.global [%0], [%1], 16, %2;"
        :: "r"(dst), "l"(src), "r"(sz) : "memory");
}
__device__ __forceinline__ void ldsm_x4(uint32_t* r, uint32_t a) {
    asm volatile("ldmatrix.sync.aligned.m8n8.x4.shared.b16 {%0,%1,%2,%3}, [%4];"
        : "=r"(r[0]), "=r"(r[1]), "=r"(r[2]), "=r"(r[3]) : "r"(a));
}
__device__ __forceinline__ void mma_bf16(float* c, const uint32_t* a, const uint32_t* b) {
    asm volatile("mma.sync.aligned.m16n8k16.row.col.f32.bf16.bf16.f32 "
        "{%0,%1,%2,%3}, {%4,%5,%6,%7}, {%8,%9}, {%0,%1,%2,%3};"
        : "+f"(c[0]), "+f"(c[1]), "+f"(c[2]), "+f"(c[3])
        : "r"(a[0]), "r"(a[1]), "r"(a[2]), "r"(a[3]), "r"(b[0]), "r"(b[1]));
}

__global__ void __launch_bounds__(256, 3)
tgemm(const __nv_bfloat16* __restrict__ Ah, const __nv_bfloat16* __restrict__ Al,
      int lda,
      const __nv_bfloat16* __restrict__ Bh, const __nv_bfloat16* __restrict__ Bl,
      int ldb, int K, int M,
      float* __restrict__ C, int ldc,
      const float* __restrict__ bias,
      const float* __restrict__ cbias, const int* __restrict__ cnt,
      const float* __restrict__ addend, int addld, int relu,
      __nv_bfloat16* __restrict__ outHi, __nv_bfloat16* __restrict__ outLo,
      const float* __restrict__ projW, const float* __restrict__ projB,
      float* __restrict__ projOut) {
    extern __shared__ char smem[];
    uint32_t sb = smem_u32(smem);
    int tid = threadIdx.x;
    int wid = tid >> 5, lane = tid & 31;
    int bm = blockIdx.y * 64;
    int bn = blockIdx.x * 128;
    int wr = wid & 1;        // M warp (0..1), 32 rows each
    int wc = wid >> 1;       // N warp (0..3), 32 cols each

    const __nv_bfloat16* srcs[4] = {Ah, Al, Bh, Bl};
    const int toff[4] = {0, TILE_A, 2 * TILE_A, 2 * TILE_A + TILE_B};

    auto issue = [&](int kc, int stg) {
        int k0 = kc * 32;
        #pragma unroll
        for (int u = 0; u < 6; u++) {
            int idx = tid + u * 256;          // 0..1535
            int tile, row;
            if (idx < 512) { tile = idx >> 8; row = (idx & 255) >> 2; }
            else { tile = 2 + ((idx - 512) >> 9); row = ((idx - 512) & 511) >> 2; }
            int c = idx & 3;
            int gr, maxr;
            if (tile < 2) { gr = bm + row; maxr = M; }
            else          { gr = bn + row; maxr = 1 << 30; }
            const __nv_bfloat16* s = srcs[tile] +
                (size_t)gr * ((tile < 2) ? lda : ldb) + k0 + c * 8;
            uint32_t d = sb + stg * STAGE_B + toff[tile] + row * (TPITCH * 2) + c * 16;
            cp16(d, s, (gr < maxr) ? 16 : 0);
        }
        asm volatile("cp.async.commit_group;" ::: "memory");
    };

    float acc[2][4][4] = {};
    int nT = K / 32;

    issue(0, 0);
    for (int t = 0; t < nT; t++) {
        int stg = t & 1;
        if (t + 1 < nT) {
            issue(t + 1, stg ^ 1);
            asm volatile("cp.async.wait_group 1;" ::: "memory");
        } else {
            asm volatile("cp.async.wait_group 0;" ::: "memory");
        }
        __syncthreads();

        uint32_t baseAH = sb + stg * STAGE_B + toff[0];
        uint32_t baseAL = sb + stg * STAGE_B + toff[1];
        uint32_t baseBH = sb + stg * STAGE_B + toff[2];
        uint32_t baseBL = sb + stg * STAGE_B + toff[3];

        #pragma unroll
        for (int ks = 0; ks < 2; ks++) {
            uint32_t aH[2][4], aL[2][4], bH[2][4], bL[2][4];
            int acol = (ks * 16 + (lane >> 4) * 8) * 2;
            int bcol = (ks * 16 + ((lane >> 3) & 1) * 8) * 2;
            #pragma unroll
            for (int mi = 0; mi < 2; mi++) {
                int arow = wr * 32 + mi * 16 + (lane & 15);
                ldsm_x4(aH[mi], baseAH + arow * (TPITCH * 2) + acol);
                ldsm_x4(aL[mi], baseAL + arow * (TPITCH * 2) + acol);
            }
            // B: x4 load covers two consecutive 8-row n-tiles
            #pragma unroll
            for (int np = 0; np < 2; np++) {
                int brow = wc * 32 + np * 16 + ((lane >> 4) & 1) * 8 + (lane & 7);
                ldsm_x4(bH[np], baseBH + brow * (TPITCH * 2) + bcol);
                ldsm_x4(bL[np], baseBL + brow * (TPITCH * 2) + bcol);
            }
            #pragma unroll
            for (int mi = 0; mi < 2; mi++)
                #pragma unroll
                for (int ni = 0; ni < 4; ni++) {
                    const uint32_t* bh_ = &bH[ni >> 1][(ni & 1) * 2];
                    const uint32_t* bl_ = &bL[ni >> 1][(ni & 1) * 2];
                    mma_bf16(acc[mi][ni], aH[mi], bh_);
                    mma_bf16(acc[mi][ni], aH[mi], bl_);
                    mma_bf16(acc[mi][ni], aL[mi], bh_);
                }
        }
        __syncthreads();
    }

    // ---- epilogue ----
    float* pbuf = (float*)smem;               // 64 rows x 2 proj accumulators
    if (projOut) {
        for (int i = tid; i < 128; i += 256) pbuf[i] = 0.f;
        __syncthreads();
    }
    float pacc[2][2][2] = {};
    #pragma unroll
    for (int mi = 0; mi < 2; mi++) {
        #pragma unroll
        for (int half = 0; half < 2; half++) {
            int gm = bm + wr * 32 + mi * 16 + (lane >> 2) + half * 8;
            if (gm >= M) continue;
            bool cb = (cbias != nullptr) && (cnt[gm] > 0);
            #pragma unroll
            for (int ni = 0; ni < 4; ni++) {
                #pragma unroll
                for (int e = 0; e < 2; e++) {
                    int gn = bn + wc * 32 + ni * 8 + (lane & 3) * 2 + e;
                    float v = acc[mi][ni][half * 2 + e];
                    if (bias)   v += __ldg(&bias[gn]);
                    if (cb)     v += __ldg(&cbias[gn]);
                    if (addend) v += addend[(size_t)gm * addld + gn];
                    if (relu)   v = fmaxf(v, 0.f);
                    if (C) C[(size_t)gm * ldc + gn] = v;
                    if (outHi) {
                        __nv_bfloat16 h = __float2bfloat16(v);
                        outHi[(size_t)gm * 128 + gn] = h;
                        outLo[(size_t)gm * 128 + gn] =
                            __float2bfloat16(v - __bfloat162float(h));
                    }
                    if (projOut) {
                        pacc[mi][half][0] = fmaf(v, __ldg(&projW[gn * 2 + 0]),
                                                 pacc[mi][half][0]);
                        pacc[mi][half][1] = fmaf(v, __ldg(&projW[gn * 2 + 1]),
                                                 pacc[mi][half][1]);
                    }
                }
            }
        }
    }
    if (projOut) {
        #pragma unroll
        for (int mi = 0; mi < 2; mi++)
            #pragma unroll
            for (int half = 0; half < 2; half++) {
                int rl = wr * 32 + mi * 16 + (lane >> 2) + half * 8;
                if (bm + rl < M) {
                    atomicAdd(&pbuf[rl * 2 + 0], pacc[mi][half][0]);
                    atomicAdd(&pbuf[rl * 2 + 1], pacc[mi][half][1]);
                }
            }
        __syncthreads();
        if (tid < 128) {
            int r = tid >> 1, c = tid & 1;
            if (bm + r < M)
                projOut[(bm + r) * 2 + c] = pbuf[tid] + __ldg(&projB[c]);
        }
    }
}

// ---------------- pairwise squared distances -------------------------------
__global__ void dist_kernel(const float* __restrict__ proj,
                            const int* __restrict__ idxs,
                            float* __restrict__ out) {
    int i = blockIdx.x * blockDim.x + threadIdx.x;
    if (i >= EE) return;
    int n  = i / (KK - 1);
    int nb = idxs[i];
    float dx = proj[n * 2 + 0] - proj[nb * 2 + 0];
    float dy = proj[n * 2 + 1] - proj[nb * 2 + 1];
    out[i] = dx * dx + dy * dy;
}

// ============================ launch ========================================
extern "C" void kernel_launch(void* const* d_in, const int* in_sizes, int n_in,
                              void* d_out, int out_size) {
    const float* x     = (const float*)d_in[0];
    const float* ea    = (const float*)d_in[1];
    const int*   idxs  = (const int*)  d_in[2];
    const float* l1mw1 = (const float*)d_in[3];   // [785,128]
    const float* l1mb1 = (const float*)d_in[4];
    const float* l1mw2 = (const float*)d_in[5];   // [128,784]
    const float* l1mb2 = (const float*)d_in[6];
    const float* l1nw1 = (const float*)d_in[7];   // [1568,128]
    const float* l1nb1 = (const float*)d_in[8];
    const float* l1nw2 = (const float*)d_in[9];   // [128,128]
    const float* l1nb2 = (const float*)d_in[10];
    const float* l2mw1 = (const float*)d_in[11];  // [129,128]
    const float* l2mb1 = (const float*)d_in[12];
    const float* l2mw2 = (const float*)d_in[13];  // [128,128]
    const float* l2mb2 = (const float*)d_in[14];
    const float* l2nw1 = (const float*)d_in[15];  // [256,128]
    const float* l2nb1 = (const float*)d_in[16];
    const float* l2nw2 = (const float*)d_in[17];  // [128,2]
    const float* l2nb2 = (const float*)d_in[18];
    float* out = (float*)d_out;

    __nv_bfloat16 *xh, *xl, *Wt1h, *Wt1l, *Wf1h, *Wf1l, *Wf2h, *Wf2l, *Whth, *Whtl;
    __nv_bfloat16 *hbh, *hbl, *hidh, *hidl;
    float *XW, *HW2, *proj, *bf1, *bf2, *bh;
    int *csr;
    cudaGetSymbolAddress((void**)&xh,   g_xh);
    cudaGetSymbolAddress((void**)&xl,   g_xl);
    cudaGetSymbolAddress((void**)&Wt1h, g_Wt1h);
    cudaGetSymbolAddress((void**)&Wt1l, g_Wt1l);
    cudaGetSymbolAddress((void**)&Wf1h, g_Wf1h);
    cudaGetSymbolAddress((void**)&Wf1l, g_Wf1l);
    cudaGetSymbolAddress((void**)&Wf2h, g_Wf2h);
    cudaGetSymbolAddress((void**)&Wf2l, g_Wf2l);
    cudaGetSymbolAddress((void**)&Whth, g_Whth);
    cudaGetSymbolAddress((void**)&Whtl, g_Whtl);
    cudaGetSymbolAddress((void**)&hbh,  g_hbh);
    cudaGetSymbolAddress((void**)&hbl,  g_hbl);
    cudaGetSymbolAddress((void**)&hidh, g_hidh);
    cudaGetSymbolAddress((void**)&hidl, g_hidl);
    cudaGetSymbolAddress((void**)&XW,   g_XW);
    cudaGetSymbolAddress((void**)&HW2,  g_HW2);
    cudaGetSymbolAddress((void**)&proj, g_proj);
    cudaGetSymbolAddress((void**)&bf1,  g_bf1);
    cudaGetSymbolAddress((void**)&bf2,  g_bf2);
    cudaGetSymbolAddress((void**)&bh,   g_bh);
    cudaGetSymbolAddress((void**)&csr,  g_csr);
    int* cnt = csr;   // first NN entries

    cudaFuncSetAttribute(tgemm, cudaFuncAttributeMaxDynamicSharedMemorySize, GSMEM);

    // ---- single memset for cnt/pos/counter ----
    cudaMemsetAsync(csr, 0, (2 * NN + 1) * sizeof(int));

    // ---- fold argument pack ----
    FoldArgs fa;
    fa.A[0] = l1mw2;  fa.avec[0] = l1mb2;  fa.B[0] = l1nw1 + (size_t)DD * HH;
    fa.oh[0] = Wf1h;  fa.ol[0] = Wf1l;     fa.bf[0] = bf1;
    fa.Kd[0] = DD;    fa.row_off[0] = 0;
    fa.A[1] = l2mw2;  fa.avec[1] = l2mb2;  fa.B[1] = l2nw1 + (size_t)HH * HH;
    fa.oh[1] = Wf2h;  fa.ol[1] = Wf2l;     fa.bf[1] = bf2;
    fa.Kd[1] = HH;    fa.row_off[1] = 0;
    fa.A[2] = l1nw2;  fa.avec[2] = l1nb2;  fa.B[2] = l2mw1;
    fa.oh[2] = Whth;  fa.ol[2] = Whtl;     fa.bf[2] = bh;
    fa.Kd[2] = HH;    fa.row_off[2] = 0;
    fa.A[3] = l1nw2;  fa.avec[3] = l1nb2;  fa.B[3] = l2nw1;
    fa.oh[3] = Whth;  fa.ol[3] = Whtl;     fa.bf[3] = bh + 128;
    fa.Kd[3] = HH;    fa.row_off[3] = 128;

    // ---- prep: count + conv + convT + folds in ONE launch ----
    prep_mega<<<PB_TOTAL, 256>>>(idxs, x, l1mw1, l1nw1, xh, xl, Wt1h, Wt1l, fa);
    offs_kernel<<<(NN + 255) / 256, 256>>>();
    fill_kernel<<<(EE + 255) / 256, 256>>>(idxs, ea);

    // ---- layer 1 ----
    // XW = x @ [W1x_msg | W1a_node]   [N,256]
    tgemm<<<dim3(2, 157), 256, GSMEM>>>(
        xh, xl, KPAD, Wt1h, Wt1l, KPAD, KPAD, NN,
        XW, 256, nullptr, nullptr, nullptr, nullptr, 0, 0,
        nullptr, nullptr, nullptr, nullptr, nullptr);
    // hbar = mean_e relu(XW[:, :128][src] + a*we1 + b1)   (bf16 pair)
    edge_agg<<<(NN * HH + 255) / 256, 256>>>(XW, 256, l1mw1 + (size_t)DD * HH,
                                             l1mb1, hbh, hbl);
    // hidden1 = relu(hbar@Wf1 + XW[:,128:] + l1nb1 + [cnt>0]*bf1) -> bf16 pair
    tgemm<<<dim3(1, 157), 256, GSMEM>>>(
        hbh, hbl, HH, Wf1h, Wf1l, HH, HH, NN,
        nullptr, 0, l1nb1, bf1, cnt, XW + 128, 256, 1,
        hidh, hidl, nullptr, nullptr, nullptr);

    // ---- layer 2 (intermediate h folded away) ----
    // HW2 = hidden1 @ Wh + bh          [N,256]
    tgemm<<<dim3(2, 157), 256, GSMEM>>>(
        hidh, hidl, HH, Whth, Whtl, HH, HH, NN,
        HW2, 256, bh, nullptr, nullptr, nullptr, 0, 0,
        nullptr, nullptr, nullptr, nullptr, nullptr);
    // hbar2 = mean_e relu(HW2[:, :128][src] + a*we2 + b1)
    edge_agg<<<(NN * HH + 255) / 256, 256>>>(HW2, 256, l2mw1 + (size_t)HH * HH,
                                             l2mb1, hbh, hbl);
    // hidden2 = relu(hbar2@Wf2 + HW2[:,128:] + l2nb1 + [cnt>0]*bf2) -> fused proj
    tgemm<<<dim3(1, 157), 256, GSMEM>>>(
        hbh, hbl, HH, Wf2h, Wf2l, HH, HH, NN,
        nullptr, 0, l2nb1, bf2, cnt, HW2 + 128, 256, 1,
        nullptr, nullptr, l2nw2, l2nb2, proj);

    // ---- output ----
    dist_kernel<<<(EE + 255) / 256, 256>>>(proj, idxs, out);
}